// round 11
// baseline (speedup 1.0000x reference)
#include <cuda_runtime.h>
#include <cuda_bf16.h>
#include <math.h>
#include <stdint.h>

// Problem constants
#define BB   2
#define SS   2048
#define DD   1024
#define HH   16
#define DK   64
#define NROWS (BB*SS)   // 4096

typedef unsigned long long u64;

// Scratch (allocation-free rule: device globals) — bf16 split pairs
__device__ __nv_bfloat16 g_AQhi[NROWS*DD];
__device__ __nv_bfloat16 g_AQlo[NROWS*DD];
__device__ __nv_bfloat16 g_AKhi[NROWS*DD];
__device__ __nv_bfloat16 g_AKlo[NROWS*DD];
__device__ __nv_bfloat16 g_AVhi[NROWS*DD];
__device__ __nv_bfloat16 g_AVlo[NROWS*DD];
__device__ __nv_bfloat16 g_WQhi[DD*DD];
__device__ __nv_bfloat16 g_WQlo[DD*DD];
__device__ __nv_bfloat16 g_WKhi[DD*DD];
__device__ __nv_bfloat16 g_WKlo[DD*DD];
__device__ __nv_bfloat16 g_WVhi[DD*DD];
__device__ __nv_bfloat16 g_WVlo[DD*DD];
__device__ __nv_bfloat16 g_WOhi[DD*DD];
__device__ __nv_bfloat16 g_WOlo[DD*DD];
__device__ __nv_bfloat16 g_Qhi[NROWS*DD];
__device__ __nv_bfloat16 g_Qlo[NROWS*DD];
__device__ __nv_bfloat16 g_Khi[NROWS*DD];
__device__ __nv_bfloat16 g_Klo[NROWS*DD];
__device__ __nv_bfloat16 g_Vhi[NROWS*DD];
__device__ __nv_bfloat16 g_Vlo[NROWS*DD];
__device__ __nv_bfloat16 g_Chi[NROWS*DD];
__device__ __nv_bfloat16 g_Clo[NROWS*DD];

// ---------------------------------------------------------------------------
// Base-ISA helpers: ldmatrix + mma.sync + cp.async (all compile for sm_103)
// ---------------------------------------------------------------------------
__device__ __forceinline__ uint32_t smem_u32(const void* p) {
    uint32_t a;
    asm("{ .reg .u64 t; cvta.to.shared.u64 t, %1; cvt.u32.u64 %0, t; }" : "=r"(a) : "l"(p));
    return a;
}
__device__ __forceinline__ void ldsm_x4(uint32_t& r0, uint32_t& r1, uint32_t& r2,
                                        uint32_t& r3, uint32_t addr) {
    asm volatile("ldmatrix.sync.aligned.m8n8.x4.shared.b16 {%0,%1,%2,%3}, [%4];"
                 : "=r"(r0), "=r"(r1), "=r"(r2), "=r"(r3) : "r"(addr));
}
__device__ __forceinline__ void ldsm_x4t(uint32_t& r0, uint32_t& r1, uint32_t& r2,
                                         uint32_t& r3, uint32_t addr) {
    asm volatile("ldmatrix.sync.aligned.m8n8.x4.trans.shared.b16 {%0,%1,%2,%3}, [%4];"
                 : "=r"(r0), "=r"(r1), "=r"(r2), "=r"(r3) : "r"(addr));
}
__device__ __forceinline__ void mma_bf16(float& c0, float& c1, float& c2, float& c3,
                                         uint32_t a0, uint32_t a1, uint32_t a2, uint32_t a3,
                                         uint32_t b0, uint32_t b1) {
    asm volatile("mma.sync.aligned.m16n8k16.row.col.f32.bf16.bf16.f32 "
                 "{%0,%1,%2,%3}, {%4,%5,%6,%7}, {%8,%9}, {%0,%1,%2,%3};"
                 : "+f"(c0), "+f"(c1), "+f"(c2), "+f"(c3)
                 : "r"(a0), "r"(a1), "r"(a2), "r"(a3), "r"(b0), "r"(b1));
}
__device__ __forceinline__ void cp16(uint32_t saddr, const void* g) {
    asm volatile("cp.async.cg.shared.global [%0], [%1], 16;" :: "r"(saddr), "l"(g));
}
#define CP_COMMIT() asm volatile("cp.async.commit_group;" ::: "memory")
#define CP_WAIT0()  asm volatile("cp.async.wait_group 0;"  ::: "memory")

__device__ __forceinline__ float ex2(float x) {
    float r; asm("ex2.approx.f32 %0, %1;" : "=f"(r) : "f"(x)); return r;
}

// split a pair of fp32 into bf16x2 hi and bf16x2 lo (packed uint32)
__device__ __forceinline__ void split2(float a, float b, uint32_t& hi, uint32_t& lo) {
    __nv_bfloat162 h = __float22bfloat162_rn(make_float2(a, b));
    float2 hf = __bfloat1622float2(h);
    __nv_bfloat162 l = __float22bfloat162_rn(make_float2(a - hf.x, b - hf.y));
    hi = *(uint32_t*)&h;
    lo = *(uint32_t*)&l;
}

// ============================================================================
// Fused fp32 -> (bf16 hi, lo) splits: 3 inputs / 4 weights in one launch each
// ============================================================================
struct SplitParams {
    const float* x[4];
    __nv_bfloat16* hi[4];
    __nv_bfloat16* lo[4];
};

__global__ __launch_bounds__(256)
void split_multi(SplitParams p, int n4_each)
{
    int gi = blockIdx.x * blockDim.x + threadIdx.x;
    const int which = gi / n4_each;
    const int i = gi - which * n4_each;
    const float* x = p.x[which];
    float4 v = ((const float4*)x)[i];
    uint2 hh, ll;
    split2(v.x, v.y, hh.x, ll.x);
    split2(v.z, v.w, hh.y, ll.y);
    ((uint2*)p.hi[which])[i] = hh;
    ((uint2*)p.lo[which])[i] = ll;
}

// ============================================================================
// Tensor-core GEMM, cp.async 2-stage pipelined, bf16 split x3:
//   C[M,N] = A[M,K] * W[N,K]^T + bias[N]
// Block tile 128x128, K-chunk 32. 8 warps, warp tile 64x32.
// Batched variant (z selects projection) and single variant share the body.
// ============================================================================
#define TBK 32
#define TROW 40                  // smem row stride (bf16): 80B, conflict-free ldmatrix
#define GTILEB (128*TROW*2)      // bytes per tile array
#define GS_TOTAL (2*4*GTILEB)    // 2 stages x 4 arrays = 81920 B

struct QKVParams {
    const __nv_bfloat16* Ah[3];
    const __nv_bfloat16* Al[3];
    const __nv_bfloat16* Wh[3];
    const __nv_bfloat16* Wl[3];
    const float* bias[3];
    __nv_bfloat16* Ch[3];
    __nv_bfloat16* Cl[3];
};

__device__ __forceinline__ void gemm_body(
    const __nv_bfloat16* __restrict__ Ah, const __nv_bfloat16* __restrict__ Al,
    const __nv_bfloat16* __restrict__ Bh, const __nv_bfloat16* __restrict__ Bl,
    const float* __restrict__ bias, float* __restrict__ C,
    __nv_bfloat16* __restrict__ Chi, __nv_bfloat16* __restrict__ Clo,
    int N, int K, int splitOut, char* dynsm)
{
    const uint32_t uS = smem_u32(dynsm);
    const int t    = threadIdx.x;
    const int wid  = t >> 5;
    const int lane = t & 31;
    const int m0 = blockIdx.y * 128;
    const int n0 = blockIdx.x * 128;
    const int wm = (wid & 1) * 64;
    const int wn = (wid >> 1) * 32;
    const int nchunk = K / TBK;

    const int lrow0 = t >> 2;            // 0..63
    const int lcc   = (t & 3) * 8;       // bf16 col: 0,8,16,24

#define G_ISSUE(c, s) do {                                                     \
        const int _k0 = (c) * TBK;                                             \
        _Pragma("unroll")                                                      \
        for (int _p = 0; _p < 2; _p++) {                                       \
            const int _row = lrow0 + _p * 64;                                  \
            const uint32_t _so = (uint32_t)((_row * TROW + lcc) * 2);          \
            const size_t _ga = (size_t)(m0 + _row) * K + _k0 + lcc;            \
            const size_t _gb = (size_t)(n0 + _row) * K + _k0 + lcc;            \
            const uint32_t _b = uS + (uint32_t)((s) * 4) * GTILEB;             \
            cp16(_b + 0 * GTILEB + _so, Ah + _ga);                             \
            cp16(_b + 1 * GTILEB + _so, Al + _ga);                             \
            cp16(_b + 2 * GTILEB + _so, Bh + _gb);                             \
            cp16(_b + 3 * GTILEB + _so, Bl + _gb);                             \
        }                                                                      \
        CP_COMMIT();                                                           \
    } while (0)

    float acc[4][4][4];
#pragma unroll
    for (int i = 0; i < 4; i++)
#pragma unroll
        for (int j = 0; j < 4; j++)
#pragma unroll
            for (int r = 0; r < 4; r++) acc[i][j][r] = 0.f;

    G_ISSUE(0, 0);

    for (int c = 0; c < nchunk; c++) {
        const int s = c & 1;
        CP_WAIT0();
        __syncthreads();   // single barrier per chunk: orders prev reads vs next writes
        if (c + 1 < nchunk) G_ISSUE(c + 1, 1 - s);

        const uint32_t uAh = uS + (uint32_t)(s * 4 + 0) * GTILEB;
        const uint32_t uAl = uS + (uint32_t)(s * 4 + 1) * GTILEB;
        const uint32_t uBh = uS + (uint32_t)(s * 4 + 2) * GTILEB;
        const uint32_t uBl = uS + (uint32_t)(s * 4 + 3) * GTILEB;

#pragma unroll
        for (int ks = 0; ks < 2; ks++) {
            uint32_t ah[4][4], al[4][4];
#pragma unroll
            for (int ma = 0; ma < 4; ma++) {
                const int row = wm + ma * 16 + (lane & 15);
                const uint32_t off = (uint32_t)(row * TROW * 2 + ks * 32 + (lane >> 4) * 16);
                ldsm_x4(ah[ma][0], ah[ma][1], ah[ma][2], ah[ma][3], uAh + off);
                ldsm_x4(al[ma][0], al[ma][1], al[ma][2], al[ma][3], uAl + off);
            }
            uint32_t bh[4][2], bl[4][2];
#pragma unroll
            for (int np = 0; np < 2; np++) {
                const int m = lane >> 3;
                const int row = wn + np * 16 + (m >> 1) * 8 + (lane & 7);
                const uint32_t off = (uint32_t)(row * TROW * 2 + ks * 32 + (m & 1) * 16);
                ldsm_x4(bh[np*2][0], bh[np*2][1], bh[np*2+1][0], bh[np*2+1][1], uBh + off);
                ldsm_x4(bl[np*2][0], bl[np*2][1], bl[np*2+1][0], bl[np*2+1][1], uBl + off);
            }
#pragma unroll
            for (int ma = 0; ma < 4; ma++)
#pragma unroll
                for (int na = 0; na < 4; na++) {
                    float* cc = acc[ma][na];
                    mma_bf16(cc[0], cc[1], cc[2], cc[3],
                             ah[ma][0], ah[ma][1], ah[ma][2], ah[ma][3],
                             bh[na][0], bh[na][1]);
                    mma_bf16(cc[0], cc[1], cc[2], cc[3],
                             ah[ma][0], ah[ma][1], ah[ma][2], ah[ma][3],
                             bl[na][0], bl[na][1]);
                    mma_bf16(cc[0], cc[1], cc[2], cc[3],
                             al[ma][0], al[ma][1], al[ma][2], al[ma][3],
                             bh[na][0], bh[na][1]);
                }
        }
    }

    const int g = lane >> 2;
    const int q = lane & 3;
#pragma unroll
    for (int ma = 0; ma < 4; ma++) {
#pragma unroll
        for (int na = 0; na < 4; na++) {
            const int col = n0 + wn + na * 8 + q * 2;
            const float b0 = bias[col], b1 = bias[col + 1];
            const int r0 = m0 + wm + ma * 16 + g;
            const float v00 = acc[ma][na][0] + b0, v01 = acc[ma][na][1] + b1;
            const float v10 = acc[ma][na][2] + b0, v11 = acc[ma][na][3] + b1;
            if (splitOut) {
                uint32_t h, l;
                split2(v00, v01, h, l);
                *(uint32_t*)(Chi + (size_t)r0 * N + col) = h;
                *(uint32_t*)(Clo + (size_t)r0 * N + col) = l;
                split2(v10, v11, h, l);
                *(uint32_t*)(Chi + (size_t)(r0 + 8) * N + col) = h;
                *(uint32_t*)(Clo + (size_t)(r0 + 8) * N + col) = l;
            } else {
                float* d0 = C + (size_t)r0 * N + col;
                d0[0] = v00; d0[1] = v01;
                float* d1 = C + (size_t)(r0 + 8) * N + col;
                d1[0] = v10; d1[1] = v11;
            }
        }
    }
#undef G_ISSUE
}

__global__ __launch_bounds__(256)
void gemm_qkv(QKVParams p)
{
    extern __shared__ char dynsm[];
    const int z = blockIdx.z;
    gemm_body(p.Ah[z], p.Al[z], p.Wh[z], p.Wl[z], p.bias[z],
              nullptr, p.Ch[z], p.Cl[z], DD, DD, 1, dynsm);
}

__global__ __launch_bounds__(256)
void gemm_o(const __nv_bfloat16* __restrict__ Ah, const __nv_bfloat16* __restrict__ Al,
            const __nv_bfloat16* __restrict__ Bh, const __nv_bfloat16* __restrict__ Bl,
            const float* __restrict__ bias, float* __restrict__ C)
{
    extern __shared__ char dynsm[];
    gemm_body(Ah, Al, Bh, Bl, bias, C, nullptr, nullptr, DD, DD, 0, dynsm);
}

// ============================================================================
// Flash attention on mma.sync, cp.async double-buffered K/V, x4 ldmatrix.
// Block: 128 q-rows, 64-key tiles. 8 warps = 16 rows x all 64 keys each.
// One __syncthreads per key tile. P stays in registers. exp2-domain softmax.
// ============================================================================
#define FST 72                        // smem row stride (bf16): 144 B
#define FSTB (FST*2)
#define QTILEB (128*FSTB)             // 36864 B per Q array
#define KTILEB (64*FSTB)              // 9216 B per K/V array per stage
#define FKV (2*QTILEB)
#define FMS (FKV + 8*KTILEB)          // int ms[2][64]
#define FLASH_SMEM_BYTES (FMS + 512)

__global__ __launch_bounds__(256, 2)
void flash_tc(const __nv_bfloat16* __restrict__ Qh, const __nv_bfloat16* __restrict__ Ql,
              const __nv_bfloat16* __restrict__ Kh, const __nv_bfloat16* __restrict__ Kl,
              const __nv_bfloat16* __restrict__ Vh, const __nv_bfloat16* __restrict__ Vl,
              const int* __restrict__ mask,
              __nv_bfloat16* __restrict__ Chi, __nv_bfloat16* __restrict__ Clo)
{
    extern __shared__ char dynsm[];
    const uint32_t uS = smem_u32(dynsm);
    const uint32_t uQh = uS, uQl = uS + QTILEB;
    int* ms = (int*)(dynsm + FMS);

    const int t    = threadIdx.x;
    const int wid  = t >> 5;
    const int lane = t & 31;
    const int g    = lane >> 2;
    const int q    = lane & 3;
    const int i0   = blockIdx.x * 128;
    const int h    = blockIdx.y;
    const int b    = blockIdx.z;
    const size_t base = (size_t)b * SS * DD + (size_t)h * DK;

    // Load Q tile (plain stores; first loop-top sync publishes them)
    {
        __nv_bfloat16* sQh = (__nv_bfloat16*)dynsm;
        __nv_bfloat16* sQl = sQh + 128 * FST;
#pragma unroll
        for (int p = 0; p < 4; p++) {
            const int idx = t + p * 256;
            const int row = idx >> 3;
            const int c   = (idx & 7) * 8;
            const size_t ga = base + (size_t)(i0 + row) * DD + c;
            *(uint4*)(sQh + row * FST + c) = *(const uint4*)(Qh + ga);
            *(uint4*)(sQl + row * FST + c) = *(const uint4*)(Ql + ga);
        }
    }

    const int lrow = t >> 3;         // 0..31
    const int lcc  = (t & 7) * 8;    // bf16 col

#define F_ISSUE(jt, s) do {                                                    \
        const int _j0 = (jt) * 64;                                             \
        _Pragma("unroll")                                                      \
        for (int _p = 0; _p < 2; _p++) {                                       \
            const int _row = lrow + _p * 32;                                   \
            const size_t _gk = base + (size_t)(_j0 + _row) * DD + lcc;         \
            const uint32_t _so = (uint32_t)(_row * FSTB + lcc * 2);            \
            cp16(uS + FKV + (uint32_t)(0 * 2 + (s)) * KTILEB + _so, Kh + _gk); \
            cp16(uS + FKV + (uint32_t)(1 * 2 + (s)) * KTILEB + _so, Kl + _gk); \
            cp16(uS + FKV + (uint32_t)(2 * 2 + (s)) * KTILEB + _so, Vh + _gk); \
            cp16(uS + FKV + (uint32_t)(3 * 2 + (s)) * KTILEB + _so, Vl + _gk); \
        }                                                                      \
        if (t < 16)                                                            \
            asm volatile("cp.async.ca.shared.global [%0], [%1], 16;"           \
                :: "r"(uS + FMS + (uint32_t)(s) * 256 + (uint32_t)t * 16),     \
                   "l"(mask + (size_t)b * SS + _j0 + t * 4));                  \
        CP_COMMIT();                                                           \
    } while (0)

    float o[8][4];
#pragma unroll
    for (int na = 0; na < 8; na++)
#pragma unroll
        for (int r = 0; r < 4; r++) o[na][r] = 0.f;
    float m0 = -INFINITY, m1 = -INFINITY, l0 = 0.f, l1 = 0.f;
    const float scale2 = 0.125f * 1.44269504089f;  // 1/sqrt(64) * log2(e)

    F_ISSUE(0, 0);

    for (int jt = 0; jt < SS / 64; jt++) {
        const int s = jt & 1;
        CP_WAIT0();
        __syncthreads();
        if (jt + 1 < SS / 64) F_ISSUE(jt + 1, 1 - s);

        const uint32_t uKh = uS + FKV + (uint32_t)(0 * 2 + s) * KTILEB;
        const uint32_t uKl = uS + FKV + (uint32_t)(1 * 2 + s) * KTILEB;
        const uint32_t uVh = uS + FKV + (uint32_t)(2 * 2 + s) * KTILEB;
        const uint32_t uVl = uS + FKV + (uint32_t)(3 * 2 + s) * KTILEB;
        const int* msj = ms + s * 64;

        // ---- GEMM1: S[16 rows x 64 keys] per warp ----
        float sc[8][4];
#pragma unroll
        for (int na = 0; na < 8; na++)
#pragma unroll
            for (int r = 0; r < 4; r++) sc[na][r] = 0.f;

#pragma unroll
        for (int ks = 0; ks < 4; ks++) {
            uint32_t ah[4], al[4];
            const uint32_t aoff = (uint32_t)((wid * 16 + (lane & 15)) * FSTB
                                             + ks * 32 + (lane >> 4) * 16);
            ldsm_x4(ah[0], ah[1], ah[2], ah[3], uQh + aoff);
            ldsm_x4(al[0], al[1], al[2], al[3], uQl + aoff);
#pragma unroll
            for (int np = 0; np < 4; np++) {
                const int m = lane >> 3;
                const int row = np * 16 + (m >> 1) * 8 + (lane & 7);
                const uint32_t boff = (uint32_t)(row * FSTB + ks * 32 + (m & 1) * 16);
                uint32_t b0h, b1h, b2h, b3h, b0l, b1l, b2l, b3l;
                ldsm_x4(b0h, b1h, b2h, b3h, uKh + boff);
                ldsm_x4(b0l, b1l, b2l, b3l, uKl + boff);
                const int na0 = np * 2, na1 = np * 2 + 1;
                mma_bf16(sc[na0][0], sc[na0][1], sc[na0][2], sc[na0][3],
                         ah[0], ah[1], ah[2], ah[3], b0h, b1h);
                mma_bf16(sc[na0][0], sc[na0][1], sc[na0][2], sc[na0][3],
                         ah[0], ah[1], ah[2], ah[3], b0l, b1l);
                mma_bf16(sc[na0][0], sc[na0][1], sc[na0][2], sc[na0][3],
                         al[0], al[1], al[2], al[3], b0h, b1h);
                mma_bf16(sc[na1][0], sc[na1][1], sc[na1][2], sc[na1][3],
                         ah[0], ah[1], ah[2], ah[3], b2h, b3h);
                mma_bf16(sc[na1][0], sc[na1][1], sc[na1][2], sc[na1][3],
                         ah[0], ah[1], ah[2], ah[3], b2l, b3l);
                mma_bf16(sc[na1][0], sc[na1][1], sc[na1][2], sc[na1][3],
                         al[0], al[1], al[2], al[3], b2h, b3h);
            }
        }

        // ---- scale (exp2 domain) + mask ----
#pragma unroll
        for (int na = 0; na < 8; na++) {
            const int kc = na * 8 + q * 2;
            const int mk0 = msj[kc], mk1 = msj[kc + 1];
            sc[na][0] = mk0 ? sc[na][0] * scale2 : -1e9f;
            sc[na][1] = mk1 ? sc[na][1] * scale2 : -1e9f;
            sc[na][2] = mk0 ? sc[na][2] * scale2 : -1e9f;
            sc[na][3] = mk1 ? sc[na][3] * scale2 : -1e9f;
        }

        // ---- online softmax in exp2 domain (rows g, g+8; 4 lanes per row) ----
        float mx0 = -INFINITY, mx1 = -INFINITY;
#pragma unroll
        for (int na = 0; na < 8; na++) {
            mx0 = fmaxf(mx0, fmaxf(sc[na][0], sc[na][1]));
            mx1 = fmaxf(mx1, fmaxf(sc[na][2], sc[na][3]));
        }
        mx0 = fmaxf(mx0, __shfl_xor_sync(0xffffffffu, mx0, 1));
        mx0 = fmaxf(mx0, __shfl_xor_sync(0xffffffffu, mx0, 2));
        mx1 = fmaxf(mx1, __shfl_xor_sync(0xffffffffu, mx1, 1));
        mx1 = fmaxf(mx1, __shfl_xor_sync(0xffffffffu, mx1, 2));
        const float mn0 = fmaxf(m0, mx0), mn1 = fmaxf(m1, mx1);
        const float a0 = ex2(m0 - mn0), a1 = ex2(m1 - mn1);
        float sum0 = 0.f, sum1 = 0.f;
#pragma unroll
        for (int na = 0; na < 8; na++) {
            sc[na][0] = ex2(sc[na][0] - mn0); sum0 += sc[na][0];
            sc[na][1] = ex2(sc[na][1] - mn0); sum0 += sc[na][1];
            sc[na][2] = ex2(sc[na][2] - mn1); sum1 += sc[na][2];
            sc[na][3] = ex2(sc[na][3] - mn1); sum1 += sc[na][3];
        }
        sum0 += __shfl_xor_sync(0xffffffffu, sum0, 1);
        sum0 += __shfl_xor_sync(0xffffffffu, sum0, 2);
        sum1 += __shfl_xor_sync(0xffffffffu, sum1, 1);
        sum1 += __shfl_xor_sync(0xffffffffu, sum1, 2);
        l0 = l0 * a0 + sum0;
        l1 = l1 * a1 + sum1;
        m0 = mn0; m1 = mn1;
#pragma unroll
        for (int na = 0; na < 8; na++) {
            o[na][0] *= a0; o[na][1] *= a0;
            o[na][2] *= a1; o[na][3] *= a1;
        }

        // ---- GEMM2: O += P * V  (P in registers, V via ldmatrix.x4.trans) ----
#pragma unroll
        for (int kk = 0; kk < 4; kk++) {
            uint32_t ph[4], pl[4];
            split2(sc[2*kk][0],   sc[2*kk][1],   ph[0], pl[0]);
            split2(sc[2*kk][2],   sc[2*kk][3],   ph[1], pl[1]);
            split2(sc[2*kk+1][0], sc[2*kk+1][1], ph[2], pl[2]);
            split2(sc[2*kk+1][2], sc[2*kk+1][3], ph[3], pl[3]);
            const int m = lane >> 3;
#pragma unroll
            for (int np = 0; np < 4; np++) {
                const int row = kk * 16 + (m & 1) * 8 + (lane & 7);
                const int na0 = np * 2, na1 = np * 2 + 1;
                const uint32_t voff = (uint32_t)(row * FSTB + (np * 2 + (m >> 1)) * 16);
                uint32_t v0h, v1h, v2h, v3h, v0l, v1l, v2l, v3l;
                ldsm_x4t(v0h, v1h, v2h, v3h, uVh + voff);
                ldsm_x4t(v0l, v1l, v2l, v3l, uVl + voff);
                mma_bf16(o[na0][0], o[na0][1], o[na0][2], o[na0][3],
                         ph[0], ph[1], ph[2], ph[3], v0h, v1h);
                mma_bf16(o[na0][0], o[na0][1], o[na0][2], o[na0][3],
                         ph[0], ph[1], ph[2], ph[3], v0l, v1l);
                mma_bf16(o[na0][0], o[na0][1], o[na0][2], o[na0][3],
                         pl[0], pl[1], pl[2], pl[3], v0h, v1h);
                mma_bf16(o[na1][0], o[na1][1], o[na1][2], o[na1][3],
                         ph[0], ph[1], ph[2], ph[3], v2h, v3h);
                mma_bf16(o[na1][0], o[na1][1], o[na1][2], o[na1][3],
                         ph[0], ph[1], ph[2], ph[3], v2l, v3l);
                mma_bf16(o[na1][0], o[na1][1], o[na1][2], o[na1][3],
                         pl[0], pl[1], pl[2], pl[3], v2h, v3h);
            }
        }
    }

    // ---- epilogue: divide by l, write split bf16 context ----
    const float inv0 = 1.f / l0, inv1 = 1.f / l1;
    const int r0 = i0 + wid * 16 + g;
#pragma unroll
    for (int na = 0; na < 8; na++) {
        const int col = na * 8 + q * 2;
        const size_t p0 = base + (size_t)r0 * DD + col;
        const size_t p1 = base + (size_t)(r0 + 8) * DD + col;
        uint32_t hh, ll;
        split2(o[na][0] * inv0, o[na][1] * inv0, hh, ll);
        *(uint32_t*)(Chi + p0) = hh;
        *(uint32_t*)(Clo + p0) = ll;
        split2(o[na][2] * inv1, o[na][3] * inv1, hh, ll);
        *(uint32_t*)(Chi + p1) = hh;
        *(uint32_t*)(Clo + p1) = ll;
    }
}

// ============================================================================
// kernel_launch
// ============================================================================
extern "C" void kernel_launch(void* const* d_in, const int* in_sizes, int n_in,
                              void* d_out, int out_size)
{
    const float* q    = (const float*)d_in[0];
    const float* k    = (const float*)d_in[1];
    const float* v    = (const float*)d_in[2];
    const int*   mask = (const int*)  d_in[3];
    const float* wq   = (const float*)d_in[4];
    const float* bq   = (const float*)d_in[5];
    const float* wk   = (const float*)d_in[6];
    const float* bk   = (const float*)d_in[7];
    const float* wv   = (const float*)d_in[8];
    const float* bv   = (const float*)d_in[9];
    const float* wo   = (const float*)d_in[10];
    const float* bo   = (const float*)d_in[11];
    float* out = (float*)d_out;

    __nv_bfloat16 *aqh, *aql, *akh, *akl, *avh, *avl;
    __nv_bfloat16 *wqh, *wql, *wkh, *wkl, *wvh, *wvl, *woh, *wol;
    __nv_bfloat16 *qhi, *qlo, *khi, *klo, *vhi, *vlo, *chi, *clo;
    cudaGetSymbolAddress((void**)&aqh, g_AQhi);
    cudaGetSymbolAddress((void**)&aql, g_AQlo);
    cudaGetSymbolAddress((void**)&akh, g_AKhi);
    cudaGetSymbolAddress((void**)&akl, g_AKlo);
    cudaGetSymbolAddress((void**)&avh, g_AVhi);
    cudaGetSymbolAddress((void**)&avl, g_AVlo);
    cudaGetSymbolAddress((void**)&wqh, g_WQhi);
    cudaGetSymbolAddress((void**)&wql, g_WQlo);
    cudaGetSymbolAddress((void**)&wkh, g_WKhi);
    cudaGetSymbolAddress((void**)&wkl, g_WKlo);
    cudaGetSymbolAddress((void**)&wvh, g_WVhi);
    cudaGetSymbolAddress((void**)&wvl, g_WVlo);
    cudaGetSymbolAddress((void**)&woh, g_WOhi);
    cudaGetSymbolAddress((void**)&wol, g_WOlo);
    cudaGetSymbolAddress((void**)&qhi, g_Qhi);
    cudaGetSymbolAddress((void**)&qlo, g_Qlo);
    cudaGetSymbolAddress((void**)&khi, g_Khi);
    cudaGetSymbolAddress((void**)&klo, g_Klo);
    cudaGetSymbolAddress((void**)&vhi, g_Vhi);
    cudaGetSymbolAddress((void**)&vlo, g_Vlo);
    cudaGetSymbolAddress((void**)&chi, g_Chi);
    cudaGetSymbolAddress((void**)&clo, g_Clo);

    static bool attr_set = false;
    if (!attr_set) {
        cudaFuncSetAttribute(flash_tc, cudaFuncAttributeMaxDynamicSharedMemorySize,
                             FLASH_SMEM_BYTES);
        cudaFuncSetAttribute(gemm_qkv, cudaFuncAttributeMaxDynamicSharedMemorySize,
                             GS_TOTAL);
        cudaFuncSetAttribute(gemm_o, cudaFuncAttributeMaxDynamicSharedMemorySize,
                             GS_TOTAL);
        attr_set = true;
    }

    const int nA4 = NROWS * DD / 4;   // 1,048,576
    const int nW4 = DD * DD / 4;      //   262,144

    // Fused splits: 3 inputs in one launch, 4 weights in one launch
    {
        SplitParams sp{};
        sp.x[0] = q;  sp.hi[0] = aqh; sp.lo[0] = aql;
        sp.x[1] = k;  sp.hi[1] = akh; sp.lo[1] = akl;
        sp.x[2] = v;  sp.hi[2] = avh; sp.lo[2] = avl;
        sp.x[3] = q;  sp.hi[3] = aqh; sp.lo[3] = aql;  // unused (guarded by grid)
        split_multi<<<3 * nA4 / 256, 256>>>(sp, nA4);
    }
    {
        SplitParams sp{};
        sp.x[0] = wq; sp.hi[0] = wqh; sp.lo[0] = wql;
        sp.x[1] = wk; sp.hi[1] = wkh; sp.lo[1] = wkl;
        sp.x[2] = wv; sp.hi[2] = wvh; sp.lo[2] = wvl;
        sp.x[3] = wo; sp.hi[3] = woh; sp.lo[3] = wol;
        split_multi<<<4 * nW4 / 256, 256>>>(sp, nW4);
    }

    // Batched Q/K/V projections (one launch, z selects)
    {
        QKVParams p{};
        p.Ah[0] = aqh; p.Al[0] = aql; p.Wh[0] = wqh; p.Wl[0] = wql;
        p.bias[0] = bq; p.Ch[0] = qhi; p.Cl[0] = qlo;
        p.Ah[1] = akh; p.Al[1] = akl; p.Wh[1] = wkh; p.Wl[1] = wkl;
        p.bias[1] = bk; p.Ch[1] = khi; p.Cl[1] = klo;
        p.Ah[2] = avh; p.Al[2] = avl; p.Wh[2] = wvh; p.Wl[2] = wvl;
        p.bias[2] = bv; p.Ch[2] = vhi; p.Cl[2] = vlo;
        dim3 tgrid(DD / 128, NROWS / 128, 3);   // (8, 32, 3) = 768 CTAs
        gemm_qkv<<<tgrid, 256, GS_TOTAL>>>(p);
    }

    // Attention (writes split bf16 context directly)
    dim3 fgrid(SS / 128, HH, BB);        // (16, 16, 2)
    flash_tc<<<fgrid, 256, FLASH_SMEM_BYTES>>>(qhi, qlo, khi, klo, vhi, vlo, mask, chi, clo);

    // Output projection (fp32 out)
    dim3 ogrid(DD / 128, NROWS / 128);   // (8, 32)
    gemm_o<<<ogrid, 256, GS_TOTAL>>>(chi, clo, woh, wol, bo, out);
}

// round 12
// speedup vs baseline: 1.0641x; 1.0641x over previous
#include <cuda_runtime.h>
#include <cuda_bf16.h>
#include <cuda_fp16.h>
#include <math.h>
#include <stdint.h>

// Problem constants
#define BB   2
#define SS   2048
#define DD   1024
#define HH   16
#define DK   64
#define NROWS (BB*SS)   // 4096

typedef unsigned long long u64;

// Scratch (allocation-free rule: device globals)
__device__ __nv_bfloat16 g_AQhi[NROWS*DD];
__device__ __nv_bfloat16 g_AQlo[NROWS*DD];
__device__ __nv_bfloat16 g_AKhi[NROWS*DD];
__device__ __nv_bfloat16 g_AKlo[NROWS*DD];
__device__ __nv_bfloat16 g_AVhi[NROWS*DD];
__device__ __nv_bfloat16 g_AVlo[NROWS*DD];
__device__ __nv_bfloat16 g_WQhi[DD*DD];
__device__ __nv_bfloat16 g_WQlo[DD*DD];
__device__ __nv_bfloat16 g_WKhi[DD*DD];
__device__ __nv_bfloat16 g_WKlo[DD*DD];
__device__ __nv_bfloat16 g_WVhi[DD*DD];
__device__ __nv_bfloat16 g_WVlo[DD*DD];
__device__ __nv_bfloat16 g_WOhi[DD*DD];
__device__ __nv_bfloat16 g_WOlo[DD*DD];
__device__ __nv_bfloat16 g_Qhi[NROWS*DD];
__device__ __nv_bfloat16 g_Qlo[NROWS*DD];
__device__ __nv_bfloat16 g_Khi[NROWS*DD];
__device__ __nv_bfloat16 g_Klo[NROWS*DD];
__device__ __half        g_Vh2[NROWS*DD];   // V projection in fp16 limbs
__device__ __half        g_Vl2[NROWS*DD];
__device__ __nv_bfloat16 g_Chi[NROWS*DD];
__device__ __nv_bfloat16 g_Clo[NROWS*DD];

// ---------------------------------------------------------------------------
// Base-ISA helpers: ldmatrix + mma.sync + cp.async (all compile for sm_103)
// ---------------------------------------------------------------------------
__device__ __forceinline__ uint32_t smem_u32(const void* p) {
    uint32_t a;
    asm("{ .reg .u64 t; cvta.to.shared.u64 t, %1; cvt.u32.u64 %0, t; }" : "=r"(a) : "l"(p));
    return a;
}
__device__ __forceinline__ void ldsm_x4(uint32_t& r0, uint32_t& r1, uint32_t& r2,
                                        uint32_t& r3, uint32_t addr) {
    asm volatile("ldmatrix.sync.aligned.m8n8.x4.shared.b16 {%0,%1,%2,%3}, [%4];"
                 : "=r"(r0), "=r"(r1), "=r"(r2), "=r"(r3) : "r"(addr));
}
__device__ __forceinline__ void ldsm_x4t(uint32_t& r0, uint32_t& r1, uint32_t& r2,
                                         uint32_t& r3, uint32_t addr) {
    asm volatile("ldmatrix.sync.aligned.m8n8.x4.trans.shared.b16 {%0,%1,%2,%3}, [%4];"
                 : "=r"(r0), "=r"(r1), "=r"(r2), "=r"(r3) : "r"(addr));
}
__device__ __forceinline__ void mma_bf16(float& c0, float& c1, float& c2, float& c3,
                                         uint32_t a0, uint32_t a1, uint32_t a2, uint32_t a3,
                                         uint32_t b0, uint32_t b1) {
    asm volatile("mma.sync.aligned.m16n8k16.row.col.f32.bf16.bf16.f32 "
                 "{%0,%1,%2,%3}, {%4,%5,%6,%7}, {%8,%9}, {%0,%1,%2,%3};"
                 : "+f"(c0), "+f"(c1), "+f"(c2), "+f"(c3)
                 : "r"(a0), "r"(a1), "r"(a2), "r"(a3), "r"(b0), "r"(b1));
}
__device__ __forceinline__ void mma_f16(float& c0, float& c1, float& c2, float& c3,
                                        uint32_t a0, uint32_t a1, uint32_t a2, uint32_t a3,
                                        uint32_t b0, uint32_t b1) {
    asm volatile("mma.sync.aligned.m16n8k16.row.col.f32.f16.f16.f32 "
                 "{%0,%1,%2,%3}, {%4,%5,%6,%7}, {%8,%9}, {%0,%1,%2,%3};"
                 : "+f"(c0), "+f"(c1), "+f"(c2), "+f"(c3)
                 : "r"(a0), "r"(a1), "r"(a2), "r"(a3), "r"(b0), "r"(b1));
}
__device__ __forceinline__ void cp16(uint32_t saddr, const void* g) {
    asm volatile("cp.async.cg.shared.global [%0], [%1], 16;" :: "r"(saddr), "l"(g));
}
#define CP_COMMIT() asm volatile("cp.async.commit_group;" ::: "memory")
#define CP_WAIT0()  asm volatile("cp.async.wait_group 0;"  ::: "memory")

__device__ __forceinline__ float ex2(float x) {
    float r; asm("ex2.approx.f32 %0, %1;" : "=f"(r) : "f"(x)); return r;
}
// pack two fp32 into f16x2 (lo = first arg)
__device__ __forceinline__ uint32_t packh(float lo, float hi) {
    uint32_t r;
    asm("cvt.rn.f16x2.f32 %0, %1, %2;" : "=r"(r) : "f"(hi), "f"(lo));
    return r;
}

// split a pair of fp32 into bf16x2 hi and bf16x2 lo (packed uint32)
__device__ __forceinline__ void split2(float a, float b, uint32_t& hi, uint32_t& lo) {
    __nv_bfloat162 h = __float22bfloat162_rn(make_float2(a, b));
    float2 hf = __bfloat1622float2(h);
    __nv_bfloat162 l = __float22bfloat162_rn(make_float2(a - hf.x, b - hf.y));
    hi = *(uint32_t*)&h;
    lo = *(uint32_t*)&l;
}
// split a pair of fp32 into f16x2 hi and f16x2 lo (packed uint32)
__device__ __forceinline__ void split2h(float a, float b, uint32_t& hi, uint32_t& lo) {
    __half2 h = __float22half2_rn(make_float2(a, b));
    float2 hf = __half22float2(h);
    __half2 l = __float22half2_rn(make_float2(a - hf.x, b - hf.y));
    hi = *(uint32_t*)&h;
    lo = *(uint32_t*)&l;
}

// ============================================================================
// Fused fp32 -> (bf16 hi, lo) splits: 3 inputs / 4 weights in one launch each
// ============================================================================
struct SplitParams {
    const float* x[4];
    __nv_bfloat16* hi[4];
    __nv_bfloat16* lo[4];
};

__global__ __launch_bounds__(256)
void split_multi(SplitParams p, int n4_each)
{
    int gi = blockIdx.x * blockDim.x + threadIdx.x;
    const int which = gi / n4_each;
    const int i = gi - which * n4_each;
    const float* x = p.x[which];
    float4 v = ((const float4*)x)[i];
    uint2 hh, ll;
    split2(v.x, v.y, hh.x, ll.x);
    split2(v.z, v.w, hh.y, ll.y);
    ((uint2*)p.hi[which])[i] = hh;
    ((uint2*)p.lo[which])[i] = ll;
}

// ============================================================================
// Tensor-core GEMM, cp.async 2-stage pipelined, bf16 split x3:
//   C[M,N] = A[M,K] * W[N,K]^T + bias[N]
// Block tile 128x128, K-chunk 32. 8 warps, warp tile 64x32.
// outMode: 0 -> fp32 C; 1 -> bf16 limb pair; 2 -> fp16 limb pair
// ============================================================================
#define TBK 32
#define TROW 40                  // smem row stride (bf16): 80B, conflict-free ldmatrix
#define GTILEB (128*TROW*2)      // bytes per tile array
#define GS_TOTAL (2*4*GTILEB)    // 2 stages x 4 arrays = 81920 B

struct QKVParams {
    const __nv_bfloat16* Ah[3];
    const __nv_bfloat16* Al[3];
    const __nv_bfloat16* Wh[3];
    const __nv_bfloat16* Wl[3];
    const float* bias[3];
    __nv_bfloat16* Ch[3];
    __nv_bfloat16* Cl[3];
};

__device__ __forceinline__ void gemm_body(
    const __nv_bfloat16* __restrict__ Ah, const __nv_bfloat16* __restrict__ Al,
    const __nv_bfloat16* __restrict__ Bh, const __nv_bfloat16* __restrict__ Bl,
    const float* __restrict__ bias, float* __restrict__ C,
    __nv_bfloat16* __restrict__ Chi, __nv_bfloat16* __restrict__ Clo,
    int N, int K, int outMode, char* dynsm)
{
    const uint32_t uS = smem_u32(dynsm);
    const int t    = threadIdx.x;
    const int wid  = t >> 5;
    const int lane = t & 31;
    const int m0 = blockIdx.y * 128;
    const int n0 = blockIdx.x * 128;
    const int wm = (wid & 1) * 64;
    const int wn = (wid >> 1) * 32;
    const int nchunk = K / TBK;

    const int lrow0 = t >> 2;            // 0..63
    const int lcc   = (t & 3) * 8;       // bf16 col: 0,8,16,24

#define G_ISSUE(c, s) do {                                                     \
        const int _k0 = (c) * TBK;                                             \
        _Pragma("unroll")                                                      \
        for (int _p = 0; _p < 2; _p++) {                                       \
            const int _row = lrow0 + _p * 64;                                  \
            const uint32_t _so = (uint32_t)((_row * TROW + lcc) * 2);          \
            const size_t _ga = (size_t)(m0 + _row) * K + _k0 + lcc;            \
            const size_t _gb = (size_t)(n0 + _row) * K + _k0 + lcc;            \
            const uint32_t _b = uS + (uint32_t)((s) * 4) * GTILEB;             \
            cp16(_b + 0 * GTILEB + _so, Ah + _ga);                             \
            cp16(_b + 1 * GTILEB + _so, Al + _ga);                             \
            cp16(_b + 2 * GTILEB + _so, Bh + _gb);                             \
            cp16(_b + 3 * GTILEB + _so, Bl + _gb);                             \
        }                                                                      \
        CP_COMMIT();                                                           \
    } while (0)

    float acc[4][4][4];
#pragma unroll
    for (int i = 0; i < 4; i++)
#pragma unroll
        for (int j = 0; j < 4; j++)
#pragma unroll
            for (int r = 0; r < 4; r++) acc[i][j][r] = 0.f;

    G_ISSUE(0, 0);

    for (int c = 0; c < nchunk; c++) {
        const int s = c & 1;
        CP_WAIT0();
        __syncthreads();   // orders prev-iter reads of the other stage vs new writes
        if (c + 1 < nchunk) G_ISSUE(c + 1, 1 - s);

        const uint32_t uAh = uS + (uint32_t)(s * 4 + 0) * GTILEB;
        const uint32_t uAl = uS + (uint32_t)(s * 4 + 1) * GTILEB;
        const uint32_t uBh = uS + (uint32_t)(s * 4 + 2) * GTILEB;
        const uint32_t uBl = uS + (uint32_t)(s * 4 + 3) * GTILEB;

#pragma unroll
        for (int ks = 0; ks < 2; ks++) {
            uint32_t ah[4][4], al[4][4];
#pragma unroll
            for (int ma = 0; ma < 4; ma++) {
                const int row = wm + ma * 16 + (lane & 15);
                const uint32_t off = (uint32_t)(row * TROW * 2 + ks * 32 + (lane >> 4) * 16);
                ldsm_x4(ah[ma][0], ah[ma][1], ah[ma][2], ah[ma][3], uAh + off);
                ldsm_x4(al[ma][0], al[ma][1], al[ma][2], al[ma][3], uAl + off);
            }
            uint32_t bh[4][2], bl[4][2];
#pragma unroll
            for (int np = 0; np < 2; np++) {
                const int m = lane >> 3;
                const int row = wn + np * 16 + (m >> 1) * 8 + (lane & 7);
                const uint32_t off = (uint32_t)(row * TROW * 2 + ks * 32 + (m & 1) * 16);
                ldsm_x4(bh[np*2][0], bh[np*2][1], bh[np*2+1][0], bh[np*2+1][1], uBh + off);
                ldsm_x4(bl[np*2][0], bl[np*2][1], bl[np*2+1][0], bl[np*2+1][1], uBl + off);
            }
#pragma unroll
            for (int ma = 0; ma < 4; ma++)
#pragma unroll
                for (int na = 0; na < 4; na++) {
                    float* cc = acc[ma][na];
                    mma_bf16(cc[0], cc[1], cc[2], cc[3],
                             ah[ma][0], ah[ma][1], ah[ma][2], ah[ma][3],
                             bh[na][0], bh[na][1]);
                    mma_bf16(cc[0], cc[1], cc[2], cc[3],
                             ah[ma][0], ah[ma][1], ah[ma][2], ah[ma][3],
                             bl[na][0], bl[na][1]);
                    mma_bf16(cc[0], cc[1], cc[2], cc[3],
                             al[ma][0], al[ma][1], al[ma][2], al[ma][3],
                             bh[na][0], bh[na][1]);
                }
        }
    }

    const int g = lane >> 2;
    const int q = lane & 3;
#pragma unroll
    for (int ma = 0; ma < 4; ma++) {
#pragma unroll
        for (int na = 0; na < 4; na++) {
            const int col = n0 + wn + na * 8 + q * 2;
            const float b0 = bias[col], b1 = bias[col + 1];
            const int r0 = m0 + wm + ma * 16 + g;
            const float v00 = acc[ma][na][0] + b0, v01 = acc[ma][na][1] + b1;
            const float v10 = acc[ma][na][2] + b0, v11 = acc[ma][na][3] + b1;
            if (outMode == 1) {
                uint32_t h, l;
                split2(v00, v01, h, l);
                *(uint32_t*)(Chi + (size_t)r0 * N + col) = h;
                *(uint32_t*)(Clo + (size_t)r0 * N + col) = l;
                split2(v10, v11, h, l);
                *(uint32_t*)(Chi + (size_t)(r0 + 8) * N + col) = h;
                *(uint32_t*)(Clo + (size_t)(r0 + 8) * N + col) = l;
            } else if (outMode == 2) {
                __half* Hh = (__half*)Chi;
                __half* Hl = (__half*)Clo;
                uint32_t h, l;
                split2h(v00, v01, h, l);
                *(uint32_t*)(Hh + (size_t)r0 * N + col) = h;
                *(uint32_t*)(Hl + (size_t)r0 * N + col) = l;
                split2h(v10, v11, h, l);
                *(uint32_t*)(Hh + (size_t)(r0 + 8) * N + col) = h;
                *(uint32_t*)(Hl + (size_t)(r0 + 8) * N + col) = l;
            } else {
                float* d0 = C + (size_t)r0 * N + col;
                d0[0] = v00; d0[1] = v01;
                float* d1 = C + (size_t)(r0 + 8) * N + col;
                d1[0] = v10; d1[1] = v11;
            }
        }
    }
#undef G_ISSUE
}

__global__ __launch_bounds__(256)
void gemm_qkv(QKVParams p)
{
    extern __shared__ char dynsm[];
    const int z = blockIdx.z;
    gemm_body(p.Ah[z], p.Al[z], p.Wh[z], p.Wl[z], p.bias[z],
              nullptr, p.Ch[z], p.Cl[z], DD, DD, (z == 2) ? 2 : 1, dynsm);
}

__global__ __launch_bounds__(256)
void gemm_o(const __nv_bfloat16* __restrict__ Ah, const __nv_bfloat16* __restrict__ Al,
            const __nv_bfloat16* __restrict__ Bh, const __nv_bfloat16* __restrict__ Bl,
            const float* __restrict__ bias, float* __restrict__ C)
{
    extern __shared__ char dynsm[];
    gemm_body(Ah, Al, Bh, Bl, bias, C, nullptr, nullptr, DD, DD, 0, dynsm);
}

// ============================================================================
// Flash attention on mma.sync, cp.async double-buffered K/V, x4 ldmatrix.
// GEMM1: bf16 split x3 (Q,K). GEMM2: fp16 P (single) x fp16 V (2 limbs).
// Block: 128 q-rows, 64-key tiles. 8 warps = 16 rows x all 64 keys each.
// ============================================================================
#define FST 72                        // smem row stride (bf16/fp16): 144 B
#define FSTB (FST*2)
#define QTILEB (128*FSTB)             // per Q array
#define KTILEB (64*FSTB)              // per K/V array per stage
#define FKV (2*QTILEB)
#define FMS (FKV + 8*KTILEB)          // int ms[2][64]
#define FLASH_SMEM_BYTES (FMS + 512)

__global__ __launch_bounds__(256, 2)
void flash_tc(const __nv_bfloat16* __restrict__ Qh, const __nv_bfloat16* __restrict__ Ql,
              const __nv_bfloat16* __restrict__ Kh, const __nv_bfloat16* __restrict__ Kl,
              const __half* __restrict__ Vh, const __half* __restrict__ Vl,
              const int* __restrict__ mask,
              __nv_bfloat16* __restrict__ Chi, __nv_bfloat16* __restrict__ Clo)
{
    extern __shared__ char dynsm[];
    const uint32_t uS = smem_u32(dynsm);
    const uint32_t uQh = uS, uQl = uS + QTILEB;
    int* ms = (int*)(dynsm + FMS);

    const int t    = threadIdx.x;
    const int wid  = t >> 5;
    const int lane = t & 31;
    const int g    = lane >> 2;
    const int q    = lane & 3;
    const int i0   = blockIdx.x * 128;
    const int h    = blockIdx.y;
    const int b    = blockIdx.z;
    const size_t base = (size_t)b * SS * DD + (size_t)h * DK;

    // Load Q tile (plain stores; first loop-top sync publishes them)
    {
        __nv_bfloat16* sQh = (__nv_bfloat16*)dynsm;
        __nv_bfloat16* sQl = sQh + 128 * FST;
#pragma unroll
        for (int p = 0; p < 4; p++) {
            const int idx = t + p * 256;
            const int row = idx >> 3;
            const int c   = (idx & 7) * 8;
            const size_t ga = base + (size_t)(i0 + row) * DD + c;
            *(uint4*)(sQh + row * FST + c) = *(const uint4*)(Qh + ga);
            *(uint4*)(sQl + row * FST + c) = *(const uint4*)(Ql + ga);
        }
    }

    const int lrow = t >> 3;         // 0..31
    const int lcc  = (t & 7) * 8;    // 16B-elem col

#define F_ISSUE(jt, s) do {                                                    \
        const int _j0 = (jt) * 64;                                             \
        _Pragma("unroll")                                                      \
        for (int _p = 0; _p < 2; _p++) {                                       \
            const int _row = lrow + _p * 32;                                   \
            const size_t _gk = base + (size_t)(_j0 + _row) * DD + lcc;         \
            const uint32_t _so = (uint32_t)(_row * FSTB + lcc * 2);            \
            cp16(uS + FKV + (uint32_t)(0 * 2 + (s)) * KTILEB + _so, Kh + _gk); \
            cp16(uS + FKV + (uint32_t)(1 * 2 + (s)) * KTILEB + _so, Kl + _gk); \
            cp16(uS + FKV + (uint32_t)(2 * 2 + (s)) * KTILEB + _so, Vh + _gk); \
            cp16(uS + FKV + (uint32_t)(3 * 2 + (s)) * KTILEB + _so, Vl + _gk); \
        }                                                                      \
        if (t < 16)                                                            \
            asm volatile("cp.async.ca.shared.global [%0], [%1], 16;"           \
                :: "r"(uS + FMS + (uint32_t)(s) * 256 + (uint32_t)t * 16),     \
                   "l"(mask + (size_t)b * SS + _j0 + t * 4));                  \
        CP_COMMIT();                                                           \
    } while (0)

    float o[8][4];
#pragma unroll
    for (int na = 0; na < 8; na++)
#pragma unroll
        for (int r = 0; r < 4; r++) o[na][r] = 0.f;
    float m0 = -INFINITY, m1 = -INFINITY, l0 = 0.f, l1 = 0.f;
    const float scale2 = 0.125f * 1.44269504089f;  // 1/sqrt(64) * log2(e)

    F_ISSUE(0, 0);

    for (int jt = 0; jt < SS / 64; jt++) {
        const int s = jt & 1;
        CP_WAIT0();
        __syncthreads();
        if (jt + 1 < SS / 64) F_ISSUE(jt + 1, 1 - s);

        const uint32_t uKh = uS + FKV + (uint32_t)(0 * 2 + s) * KTILEB;
        const uint32_t uKl = uS + FKV + (uint32_t)(1 * 2 + s) * KTILEB;
        const uint32_t uVh = uS + FKV + (uint32_t)(2 * 2 + s) * KTILEB;
        const uint32_t uVl = uS + FKV + (uint32_t)(3 * 2 + s) * KTILEB;
        const int* msj = ms + s * 64;

        // ---- GEMM1: S[16 rows x 64 keys] per warp (bf16 x3) ----
        float sc[8][4];
#pragma unroll
        for (int na = 0; na < 8; na++)
#pragma unroll
            for (int r = 0; r < 4; r++) sc[na][r] = 0.f;

#pragma unroll
        for (int ks = 0; ks < 4; ks++) {
            uint32_t ah[4], al[4];
            const uint32_t aoff = (uint32_t)((wid * 16 + (lane & 15)) * FSTB
                                             + ks * 32 + (lane >> 4) * 16);
            ldsm_x4(ah[0], ah[1], ah[2], ah[3], uQh + aoff);
            ldsm_x4(al[0], al[1], al[2], al[3], uQl + aoff);
#pragma unroll
            for (int np = 0; np < 4; np++) {
                const int m = lane >> 3;
                const int row = np * 16 + (m >> 1) * 8 + (lane & 7);
                const uint32_t boff = (uint32_t)(row * FSTB + ks * 32 + (m & 1) * 16);
                uint32_t b0h, b1h, b2h, b3h, b0l, b1l, b2l, b3l;
                ldsm_x4(b0h, b1h, b2h, b3h, uKh + boff);
                ldsm_x4(b0l, b1l, b2l, b3l, uKl + boff);
                const int na0 = np * 2, na1 = np * 2 + 1;
                mma_bf16(sc[na0][0], sc[na0][1], sc[na0][2], sc[na0][3],
                         ah[0], ah[1], ah[2], ah[3], b0h, b1h);
                mma_bf16(sc[na0][0], sc[na0][1], sc[na0][2], sc[na0][3],
                         ah[0], ah[1], ah[2], ah[3], b0l, b1l);
                mma_bf16(sc[na0][0], sc[na0][1], sc[na0][2], sc[na0][3],
                         al[0], al[1], al[2], al[3], b0h, b1h);
                mma_bf16(sc[na1][0], sc[na1][1], sc[na1][2], sc[na1][3],
                         ah[0], ah[1], ah[2], ah[3], b2h, b3h);
                mma_bf16(sc[na1][0], sc[na1][1], sc[na1][2], sc[na1][3],
                         ah[0], ah[1], ah[2], ah[3], b2l, b3l);
                mma_bf16(sc[na1][0], sc[na1][1], sc[na1][2], sc[na1][3],
                         al[0], al[1], al[2], al[3], b2h, b3h);
            }
        }

        // ---- scale (exp2 domain) + mask ----
#pragma unroll
        for (int na = 0; na < 8; na++) {
            const int kc = na * 8 + q * 2;
            const int mk0 = msj[kc], mk1 = msj[kc + 1];
            sc[na][0] = mk0 ? sc[na][0] * scale2 : -1e9f;
            sc[na][1] = mk1 ? sc[na][1] * scale2 : -1e9f;
            sc[na][2] = mk0 ? sc[na][2] * scale2 : -1e9f;
            sc[na][3] = mk1 ? sc[na][3] * scale2 : -1e9f;
        }

        // ---- online softmax in exp2 domain (rows g, g+8; 4 lanes per row) ----
        float mx0 = -INFINITY, mx1 = -INFINITY;
#pragma unroll
        for (int na = 0; na < 8; na++) {
            mx0 = fmaxf(mx0, fmaxf(sc[na][0], sc[na][1]));
            mx1 = fmaxf(mx1, fmaxf(sc[na][2], sc[na][3]));
        }
        mx0 = fmaxf(mx0, __shfl_xor_sync(0xffffffffu, mx0, 1));
        mx0 = fmaxf(mx0, __shfl_xor_sync(0xffffffffu, mx0, 2));
        mx1 = fmaxf(mx1, __shfl_xor_sync(0xffffffffu, mx1, 1));
        mx1 = fmaxf(mx1, __shfl_xor_sync(0xffffffffu, mx1, 2));
        const float mn0 = fmaxf(m0, mx0), mn1 = fmaxf(m1, mx1);
        const float a0 = ex2(m0 - mn0), a1 = ex2(m1 - mn1);
        float sum0 = 0.f, sum1 = 0.f;
#pragma unroll
        for (int na = 0; na < 8; na++) {
            sc[na][0] = ex2(sc[na][0] - mn0); sum0 += sc[na][0];
            sc[na][1] = ex2(sc[na][1] - mn0); sum0 += sc[na][1];
            sc[na][2] = ex2(sc[na][2] - mn1); sum1 += sc[na][2];
            sc[na][3] = ex2(sc[na][3] - mn1); sum1 += sc[na][3];
        }
        sum0 += __shfl_xor_sync(0xffffffffu, sum0, 1);
        sum0 += __shfl_xor_sync(0xffffffffu, sum0, 2);
        sum1 += __shfl_xor_sync(0xffffffffu, sum1, 1);
        sum1 += __shfl_xor_sync(0xffffffffu, sum1, 2);
        l0 = l0 * a0 + sum0;
        l1 = l1 * a1 + sum1;
        m0 = mn0; m1 = mn1;
#pragma unroll
        for (int na = 0; na < 8; na++) {
            o[na][0] *= a0; o[na][1] *= a0;
            o[na][2] *= a1; o[na][3] *= a1;
        }

        // ---- GEMM2: O += P(fp16) * V(fp16 2-limb), V via ldmatrix.x4.trans ----
#pragma unroll
        for (int kk = 0; kk < 4; kk++) {
            uint32_t ph[4];
            ph[0] = packh(sc[2*kk][0],   sc[2*kk][1]);
            ph[1] = packh(sc[2*kk][2],   sc[2*kk][3]);
            ph[2] = packh(sc[2*kk+1][0], sc[2*kk+1][1]);
            ph[3] = packh(sc[2*kk+1][2], sc[2*kk+1][3]);
            const int m = lane >> 3;
#pragma unroll
            for (int np = 0; np < 4; np++) {
                const int row = kk * 16 + (m & 1) * 8 + (lane & 7);
                const int na0 = np * 2, na1 = np * 2 + 1;
                const uint32_t voff = (uint32_t)(row * FSTB + (np * 2 + (m >> 1)) * 16);
                uint32_t v0h, v1h, v2h, v3h, v0l, v1l, v2l, v3l;
                ldsm_x4t(v0h, v1h, v2h, v3h, uVh + voff);
                ldsm_x4t(v0l, v1l, v2l, v3l, uVl + voff);
                mma_f16(o[na0][0], o[na0][1], o[na0][2], o[na0][3],
                        ph[0], ph[1], ph[2], ph[3], v0h, v1h);
                mma_f16(o[na0][0], o[na0][1], o[na0][2], o[na0][3],
                        ph[0], ph[1], ph[2], ph[3], v0l, v1l);
                mma_f16(o[na1][0], o[na1][1], o[na1][2], o[na1][3],
                        ph[0], ph[1], ph[2], ph[3], v2h, v3h);
                mma_f16(o[na1][0], o[na1][1], o[na1][2], o[na1][3],
                        ph[0], ph[1], ph[2], ph[3], v2l, v3l);
            }
        }
    }

    // ---- epilogue: divide by l, write split bf16 context ----
    const float inv0 = 1.f / l0, inv1 = 1.f / l1;
    const int r0 = i0 + wid * 16 + g;
#pragma unroll
    for (int na = 0; na < 8; na++) {
        const int col = na * 8 + q * 2;
        const size_t p0 = base + (size_t)r0 * DD + col;
        const size_t p1 = base + (size_t)(r0 + 8) * DD + col;
        uint32_t hh, ll;
        split2(o[na][0] * inv0, o[na][1] * inv0, hh, ll);
        *(uint32_t*)(Chi + p0) = hh;
        *(uint32_t*)(Clo + p0) = ll;
        split2(o[na][2] * inv1, o[na][3] * inv1, hh, ll);
        *(uint32_t*)(Chi + p1) = hh;
        *(uint32_t*)(Clo + p1) = ll;
    }
}

// ============================================================================
// kernel_launch
// ============================================================================
extern "C" void kernel_launch(void* const* d_in, const int* in_sizes, int n_in,
                              void* d_out, int out_size)
{
    const float* q    = (const float*)d_in[0];
    const float* k    = (const float*)d_in[1];
    const float* v    = (const float*)d_in[2];
    const int*   mask = (const int*)  d_in[3];
    const float* wq   = (const float*)d_in[4];
    const float* bq   = (const float*)d_in[5];
    const float* wk   = (const float*)d_in[6];
    const float* bk   = (const float*)d_in[7];
    const float* wv   = (const float*)d_in[8];
    const float* bv   = (const float*)d_in[9];
    const float* wo   = (const float*)d_in[10];
    const float* bo   = (const float*)d_in[11];
    float* out = (float*)d_out;

    __nv_bfloat16 *aqh, *aql, *akh, *akl, *avh, *avl;
    __nv_bfloat16 *wqh, *wql, *wkh, *wkl, *wvh, *wvl, *woh, *wol;
    __nv_bfloat16 *qhi, *qlo, *khi, *klo, *chi, *clo;
    __half *vh2, *vl2;
    cudaGetSymbolAddress((void**)&aqh, g_AQhi);
    cudaGetSymbolAddress((void**)&aql, g_AQlo);
    cudaGetSymbolAddress((void**)&akh, g_AKhi);
    cudaGetSymbolAddress((void**)&akl, g_AKlo);
    cudaGetSymbolAddress((void**)&avh, g_AVhi);
    cudaGetSymbolAddress((void**)&avl, g_AVlo);
    cudaGetSymbolAddress((void**)&wqh, g_WQhi);
    cudaGetSymbolAddress((void**)&wql, g_WQlo);
    cudaGetSymbolAddress((void**)&wkh, g_WKhi);
    cudaGetSymbolAddress((void**)&wkl, g_WKlo);
    cudaGetSymbolAddress((void**)&wvh, g_WVhi);
    cudaGetSymbolAddress((void**)&wvl, g_WVlo);
    cudaGetSymbolAddress((void**)&woh, g_WOhi);
    cudaGetSymbolAddress((void**)&wol, g_WOlo);
    cudaGetSymbolAddress((void**)&qhi, g_Qhi);
    cudaGetSymbolAddress((void**)&qlo, g_Qlo);
    cudaGetSymbolAddress((void**)&khi, g_Khi);
    cudaGetSymbolAddress((void**)&klo, g_Klo);
    cudaGetSymbolAddress((void**)&vh2, g_Vh2);
    cudaGetSymbolAddress((void**)&vl2, g_Vl2);
    cudaGetSymbolAddress((void**)&chi, g_Chi);
    cudaGetSymbolAddress((void**)&clo, g_Clo);

    static bool attr_set = false;
    if (!attr_set) {
        cudaFuncSetAttribute(flash_tc, cudaFuncAttributeMaxDynamicSharedMemorySize,
                             FLASH_SMEM_BYTES);
        cudaFuncSetAttribute(gemm_qkv, cudaFuncAttributeMaxDynamicSharedMemorySize,
                             GS_TOTAL);
        cudaFuncSetAttribute(gemm_o, cudaFuncAttributeMaxDynamicSharedMemorySize,
                             GS_TOTAL);
        attr_set = true;
    }

    const int nA4 = NROWS * DD / 4;   // 1,048,576
    const int nW4 = DD * DD / 4;      //   262,144

    // Fused splits: 3 inputs in one launch, 4 weights in one launch
    {
        SplitParams sp{};
        sp.x[0] = q;  sp.hi[0] = aqh; sp.lo[0] = aql;
        sp.x[1] = k;  sp.hi[1] = akh; sp.lo[1] = akl;
        sp.x[2] = v;  sp.hi[2] = avh; sp.lo[2] = avl;
        sp.x[3] = q;  sp.hi[3] = aqh; sp.lo[3] = aql;  // unused (guarded by grid)
        split_multi<<<3 * nA4 / 256, 256>>>(sp, nA4);
    }
    {
        SplitParams sp{};
        sp.x[0] = wq; sp.hi[0] = wqh; sp.lo[0] = wql;
        sp.x[1] = wk; sp.hi[1] = wkh; sp.lo[1] = wkl;
        sp.x[2] = wv; sp.hi[2] = wvh; sp.lo[2] = wvl;
        sp.x[3] = wo; sp.hi[3] = woh; sp.lo[3] = wol;
        split_multi<<<4 * nW4 / 256, 256>>>(sp, nW4);
    }

    // Batched Q/K/V projections (one launch, z selects; z=2 (V) -> fp16 limbs)
    {
        QKVParams p{};
        p.Ah[0] = aqh; p.Al[0] = aql; p.Wh[0] = wqh; p.Wl[0] = wql;
        p.bias[0] = bq; p.Ch[0] = qhi; p.Cl[0] = qlo;
        p.Ah[1] = akh; p.Al[1] = akl; p.Wh[1] = wkh; p.Wl[1] = wkl;
        p.bias[1] = bk; p.Ch[1] = khi; p.Cl[1] = klo;
        p.Ah[2] = avh; p.Al[2] = avl; p.Wh[2] = wvh; p.Wl[2] = wvl;
        p.bias[2] = bv; p.Ch[2] = (__nv_bfloat16*)vh2; p.Cl[2] = (__nv_bfloat16*)vl2;
        dim3 tgrid(DD / 128, NROWS / 128, 3);   // (8, 32, 3) = 768 CTAs
        gemm_qkv<<<tgrid, 256, GS_TOTAL>>>(p);
    }

    // Attention (writes split bf16 context directly)
    dim3 fgrid(SS / 128, HH, BB);        // (16, 16, 2)
    flash_tc<<<fgrid, 256, FLASH_SMEM_BYTES>>>(qhi, qlo, khi, klo, vh2, vl2, mask, chi, clo);

    // Output projection (fp32 out)
    dim3 ogrid(DD / 128, NROWS / 128);   // (8, 32)
    gemm_o<<<ogrid, 256, GS_TOTAL>>>(chi, clo, woh, wol, bo, out);
}

// round 13
// speedup vs baseline: 1.3877x; 1.3041x over previous
#include <cuda_runtime.h>
#include <cuda_bf16.h>
#include <cuda_fp16.h>
#include <math.h>
#include <stdint.h>

// Problem constants
#define BB   2
#define SS   2048
#define DD   1024
#define HH   16
#define DK   64
#define NROWS (BB*SS)   // 4096

// Scratch (allocation-free rule: device globals) — fp16 scheme:
// A-operands single fp16; B-operands 2-limb fp16.
__device__ __half g_Aq[NROWS*DD];
__device__ __half g_Ak[NROWS*DD];
__device__ __half g_Av[NROWS*DD];
__device__ __half g_WQh[DD*DD];
__device__ __half g_WQl[DD*DD];
__device__ __half g_WKh[DD*DD];
__device__ __half g_WKl[DD*DD];
__device__ __half g_WVh[DD*DD];
__device__ __half g_WVl[DD*DD];
__device__ __half g_WOh[DD*DD];
__device__ __half g_WOl[DD*DD];
__device__ __half g_Q1[NROWS*DD];    // Q projection, single fp16 (A of GEMM1)
__device__ __half g_Kh[NROWS*DD];    // K projection, 2-limb (B of GEMM1)
__device__ __half g_Kl[NROWS*DD];
__device__ __half g_Vh[NROWS*DD];    // V projection, 2-limb (B of GEMM2)
__device__ __half g_Vl[NROWS*DD];
__device__ __half g_C1[NROWS*DD];    // context, single fp16 (A of O-proj)

// ---------------------------------------------------------------------------
// Base-ISA helpers: ldmatrix + mma.sync + cp.async (all compile for sm_103)
// ---------------------------------------------------------------------------
__device__ __forceinline__ uint32_t smem_u32(const void* p) {
    uint32_t a;
    asm("{ .reg .u64 t; cvta.to.shared.u64 t, %1; cvt.u32.u64 %0, t; }" : "=r"(a) : "l"(p));
    return a;
}
__device__ __forceinline__ void ldsm_x4(uint32_t& r0, uint32_t& r1, uint32_t& r2,
                                        uint32_t& r3, uint32_t addr) {
    asm volatile("ldmatrix.sync.aligned.m8n8.x4.shared.b16 {%0,%1,%2,%3}, [%4];"
                 : "=r"(r0), "=r"(r1), "=r"(r2), "=r"(r3) : "r"(addr));
}
__device__ __forceinline__ void ldsm_x4t(uint32_t& r0, uint32_t& r1, uint32_t& r2,
                                         uint32_t& r3, uint32_t addr) {
    asm volatile("ldmatrix.sync.aligned.m8n8.x4.trans.shared.b16 {%0,%1,%2,%3}, [%4];"
                 : "=r"(r0), "=r"(r1), "=r"(r2), "=r"(r3) : "r"(addr));
}
__device__ __forceinline__ void mma_f16(float& c0, float& c1, float& c2, float& c3,
                                        uint32_t a0, uint32_t a1, uint32_t a2, uint32_t a3,
                                        uint32_t b0, uint32_t b1) {
    asm volatile("mma.sync.aligned.m16n8k16.row.col.f32.f16.f16.f32 "
                 "{%0,%1,%2,%3}, {%4,%5,%6,%7}, {%8,%9}, {%0,%1,%2,%3};"
                 : "+f"(c0), "+f"(c1), "+f"(c2), "+f"(c3)
                 : "r"(a0), "r"(a1), "r"(a2), "r"(a3), "r"(b0), "r"(b1));
}
__device__ __forceinline__ void cp16(uint32_t saddr, const void* g) {
    asm volatile("cp.async.cg.shared.global [%0], [%1], 16;" :: "r"(saddr), "l"(g));
}
#define CP_COMMIT() asm volatile("cp.async.commit_group;" ::: "memory")
#define CP_WAIT0()  asm volatile("cp.async.wait_group 0;"  ::: "memory")

__device__ __forceinline__ float ex2(float x) {
    float r; asm("ex2.approx.f32 %0, %1;" : "=f"(r) : "f"(x)); return r;
}
// pack two fp32 into f16x2 (lo half = first arg)
__device__ __forceinline__ uint32_t packh(float lo, float hi) {
    uint32_t r;
    asm("cvt.rn.f16x2.f32 %0, %1, %2;" : "=r"(r) : "f"(hi), "f"(lo));
    return r;
}
// split a pair of fp32 into f16x2 hi and f16x2 lo (packed uint32)
__device__ __forceinline__ void split2h(float a, float b, uint32_t& hi, uint32_t& lo) {
    __half2 h = __float22half2_rn(make_float2(a, b));
    float2 hf = __half22float2(h);
    __half2 l = __float22half2_rn(make_float2(a - hf.x, b - hf.y));
    hi = *(uint32_t*)&h;
    lo = *(uint32_t*)&l;
}

// ============================================================================
// fp32 -> fp16 single conversion (3 inputs, one launch)
// ============================================================================
struct ConvParams {
    const float* x[3];
    __half* y[3];
};

__global__ __launch_bounds__(256)
void conv_half_multi(ConvParams p, int n4_each)
{
    int gi = blockIdx.x * blockDim.x + threadIdx.x;
    const int which = gi / n4_each;
    const int i = gi - which * n4_each;
    float4 v = ((const float4*)p.x[which])[i];
    uint2 o;
    o.x = packh(v.x, v.y);
    o.y = packh(v.z, v.w);
    ((uint2*)p.y[which])[i] = o;
}

// fp32 -> (fp16 hi, fp16 lo) split (4 weights, one launch)
struct SplitHParams {
    const float* x[4];
    __half* hi[4];
    __half* lo[4];
};

__global__ __launch_bounds__(256)
void split_half_multi(SplitHParams p, int n4_each)
{
    int gi = blockIdx.x * blockDim.x + threadIdx.x;
    const int which = gi / n4_each;
    const int i = gi - which * n4_each;
    float4 v = ((const float4*)p.x[which])[i];
    uint2 hh, ll;
    split2h(v.x, v.y, hh.x, ll.x);
    split2h(v.z, v.w, hh.y, ll.y);
    ((uint2*)p.hi[which])[i] = hh;
    ((uint2*)p.lo[which])[i] = ll;
}

// ============================================================================
// Tensor-core GEMM, cp.async 2-stage pipelined, fp16 asymmetric limbs:
//   C[M,N] = A[M,K] * W[N,K]^T + bias[N],  A single fp16, W 2-limb fp16.
// Block tile 128x128, K-chunk 32. 8 warps, warp tile 64x32. 2 mma per atom.
// outMode: 0 -> fp32 C; 1 -> single fp16 C1; 2 -> 2-limb fp16 (C2h, C2l)
// ============================================================================
#define TBK 32
#define TROW 40                  // smem row stride (fp16): 80B, conflict-free ldmatrix
#define GTILEB (128*TROW*2)      // 10240 bytes per tile array
#define GS_TOTAL (2*3*GTILEB)    // 2 stages x 3 arrays = 61440 B

struct QKVParams {
    const __half* A[3];
    const __half* Wh[3];
    const __half* Wl[3];
    const float* bias[3];
    __half* C1[3];
    __half* C2h[3];
    __half* C2l[3];
};

__device__ __forceinline__ void gemm_body(
    const __half* __restrict__ A,
    const __half* __restrict__ Bh, const __half* __restrict__ Bl,
    const float* __restrict__ bias, float* __restrict__ C,
    __half* __restrict__ C1, __half* __restrict__ C2h, __half* __restrict__ C2l,
    int N, int K, int outMode, char* dynsm)
{
    const uint32_t uS = smem_u32(dynsm);
    const int t    = threadIdx.x;
    const int wid  = t >> 5;
    const int lane = t & 31;
    const int m0 = blockIdx.y * 128;
    const int n0 = blockIdx.x * 128;
    const int wm = (wid & 1) * 64;
    const int wn = (wid >> 1) * 32;
    const int nchunk = K / TBK;

    const int lrow0 = t >> 2;            // 0..63
    const int lcc   = (t & 3) * 8;       // fp16 col: 0,8,16,24

#define G_ISSUE(c, s) do {                                                     \
        const int _k0 = (c) * TBK;                                             \
        _Pragma("unroll")                                                      \
        for (int _p = 0; _p < 2; _p++) {                                       \
            const int _row = lrow0 + _p * 64;                                  \
            const uint32_t _so = (uint32_t)((_row * TROW + lcc) * 2);          \
            const size_t _ga = (size_t)(m0 + _row) * K + _k0 + lcc;            \
            const size_t _gb = (size_t)(n0 + _row) * K + _k0 + lcc;            \
            const uint32_t _b = uS + (uint32_t)((s) * 3) * GTILEB;             \
            cp16(_b + 0 * GTILEB + _so, A  + _ga);                             \
            cp16(_b + 1 * GTILEB + _so, Bh + _gb);                             \
            cp16(_b + 2 * GTILEB + _so, Bl + _gb);                             \
        }                                                                      \
        CP_COMMIT();                                                           \
    } while (0)

    float acc[4][4][4];
#pragma unroll
    for (int i = 0; i < 4; i++)
#pragma unroll
        for (int j = 0; j < 4; j++)
#pragma unroll
            for (int r = 0; r < 4; r++) acc[i][j][r] = 0.f;

    G_ISSUE(0, 0);

    for (int c = 0; c < nchunk; c++) {
        const int s = c & 1;
        CP_WAIT0();
        __syncthreads();   // orders prev-iter reads of the other stage vs new writes
        if (c + 1 < nchunk) G_ISSUE(c + 1, 1 - s);

        const uint32_t uA  = uS + (uint32_t)(s * 3 + 0) * GTILEB;
        const uint32_t uBh = uS + (uint32_t)(s * 3 + 1) * GTILEB;
        const uint32_t uBl = uS + (uint32_t)(s * 3 + 2) * GTILEB;

#pragma unroll
        for (int ks = 0; ks < 2; ks++) {
            uint32_t a[4][4];
#pragma unroll
            for (int ma = 0; ma < 4; ma++) {
                const int row = wm + ma * 16 + (lane & 15);
                const uint32_t off = (uint32_t)(row * TROW * 2 + ks * 32 + (lane >> 4) * 16);
                ldsm_x4(a[ma][0], a[ma][1], a[ma][2], a[ma][3], uA + off);
            }
            uint32_t bh[4][2], bl[4][2];
#pragma unroll
            for (int np = 0; np < 2; np++) {
                const int m = lane >> 3;
                const int row = wn + np * 16 + (m >> 1) * 8 + (lane & 7);
                const uint32_t off = (uint32_t)(row * TROW * 2 + ks * 32 + (m & 1) * 16);
                ldsm_x4(bh[np*2][0], bh[np*2][1], bh[np*2+1][0], bh[np*2+1][1], uBh + off);
                ldsm_x4(bl[np*2][0], bl[np*2][1], bl[np*2+1][0], bl[np*2+1][1], uBl + off);
            }
#pragma unroll
            for (int ma = 0; ma < 4; ma++)
#pragma unroll
                for (int na = 0; na < 4; na++) {
                    float* cc = acc[ma][na];
                    mma_f16(cc[0], cc[1], cc[2], cc[3],
                            a[ma][0], a[ma][1], a[ma][2], a[ma][3],
                            bh[na][0], bh[na][1]);
                    mma_f16(cc[0], cc[1], cc[2], cc[3],
                            a[ma][0], a[ma][1], a[ma][2], a[ma][3],
                            bl[na][0], bl[na][1]);
                }
        }
    }

    const int g = lane >> 2;
    const int q = lane & 3;
#pragma unroll
    for (int ma = 0; ma < 4; ma++) {
#pragma unroll
        for (int na = 0; na < 4; na++) {
            const int col = n0 + wn + na * 8 + q * 2;
            const float b0 = bias[col], b1 = bias[col + 1];
            const int r0 = m0 + wm + ma * 16 + g;
            const float v00 = acc[ma][na][0] + b0, v01 = acc[ma][na][1] + b1;
            const float v10 = acc[ma][na][2] + b0, v11 = acc[ma][na][3] + b1;
            if (outMode == 1) {
                *(uint32_t*)(C1 + (size_t)r0 * N + col)       = packh(v00, v01);
                *(uint32_t*)(C1 + (size_t)(r0 + 8) * N + col) = packh(v10, v11);
            } else if (outMode == 2) {
                uint32_t h, l;
                split2h(v00, v01, h, l);
                *(uint32_t*)(C2h + (size_t)r0 * N + col) = h;
                *(uint32_t*)(C2l + (size_t)r0 * N + col) = l;
                split2h(v10, v11, h, l);
                *(uint32_t*)(C2h + (size_t)(r0 + 8) * N + col) = h;
                *(uint32_t*)(C2l + (size_t)(r0 + 8) * N + col) = l;
            } else {
                float* d0 = C + (size_t)r0 * N + col;
                d0[0] = v00; d0[1] = v01;
                float* d1 = C + (size_t)(r0 + 8) * N + col;
                d1[0] = v10; d1[1] = v11;
            }
        }
    }
#undef G_ISSUE
}

__global__ __launch_bounds__(256)
void gemm_qkv(QKVParams p)
{
    extern __shared__ char dynsm[];
    const int z = blockIdx.z;
    gemm_body(p.A[z], p.Wh[z], p.Wl[z], p.bias[z],
              nullptr, p.C1[z], p.C2h[z], p.C2l[z], DD, DD,
              (z == 0) ? 1 : 2, dynsm);
}

__global__ __launch_bounds__(256)
void gemm_o(const __half* __restrict__ A,
            const __half* __restrict__ Bh, const __half* __restrict__ Bl,
            const float* __restrict__ bias, float* __restrict__ C)
{
    extern __shared__ char dynsm[];
    gemm_body(A, Bh, Bl, bias, C, nullptr, nullptr, nullptr, DD, DD, 0, dynsm);
}

// ============================================================================
// Flash attention on mma.sync fp16, cp.async double-buffered K/V.
// GEMM1: Q single fp16 x K 2-limb (2 mma/atom). GEMM2: P fp16 x V 2-limb.
// Block: 128 q-rows, 64-key tiles. 8 warps = 16 rows x all 64 keys each.
// ============================================================================
#define FST 72                        // smem row stride (fp16): 144 B
#define FSTB (FST*2)
#define QTILEB (128*FSTB)             // 18432 B (single Q array)
#define KTILEB (64*FSTB)              // 9216 B per K/V array per stage
#define FKV QTILEB
#define FMS (FKV + 8*KTILEB)          // int ms[2][64]
#define FLASH_SMEM_BYTES (FMS + 512)  // 92672 B

__global__ __launch_bounds__(256, 2)
void flash_tc(const __half* __restrict__ Q1,
              const __half* __restrict__ Kh, const __half* __restrict__ Kl,
              const __half* __restrict__ Vh, const __half* __restrict__ Vl,
              const int* __restrict__ mask,
              __half* __restrict__ C1)
{
    extern __shared__ char dynsm[];
    const uint32_t uS = smem_u32(dynsm);
    const uint32_t uQ = uS;
    int* ms = (int*)(dynsm + FMS);

    const int t    = threadIdx.x;
    const int wid  = t >> 5;
    const int lane = t & 31;
    const int g    = lane >> 2;
    const int q    = lane & 3;
    const int i0   = blockIdx.x * 128;
    const int h    = blockIdx.y;
    const int b    = blockIdx.z;
    const size_t base = (size_t)b * SS * DD + (size_t)h * DK;

    // Load Q tile (plain stores; first loop-top sync publishes them)
    {
        __half* sQ = (__half*)dynsm;
#pragma unroll
        for (int p = 0; p < 4; p++) {
            const int idx = t + p * 256;
            const int row = idx >> 3;
            const int c   = (idx & 7) * 8;
            *(uint4*)(sQ + row * FST + c) =
                *(const uint4*)(Q1 + base + (size_t)(i0 + row) * DD + c);
        }
    }

    const int lrow = t >> 3;         // 0..31
    const int lcc  = (t & 7) * 8;    // fp16 col

#define F_ISSUE(jt, s) do {                                                    \
        const int _j0 = (jt) * 64;                                             \
        _Pragma("unroll")                                                      \
        for (int _p = 0; _p < 2; _p++) {                                       \
            const int _row = lrow + _p * 32;                                   \
            const size_t _gk = base + (size_t)(_j0 + _row) * DD + lcc;         \
            const uint32_t _so = (uint32_t)(_row * FSTB + lcc * 2);            \
            cp16(uS + FKV + (uint32_t)(0 * 2 + (s)) * KTILEB + _so, Kh + _gk); \
            cp16(uS + FKV + (uint32_t)(1 * 2 + (s)) * KTILEB + _so, Kl + _gk); \
            cp16(uS + FKV + (uint32_t)(2 * 2 + (s)) * KTILEB + _so, Vh + _gk); \
            cp16(uS + FKV + (uint32_t)(3 * 2 + (s)) * KTILEB + _so, Vl + _gk); \
        }                                                                      \
        if (t < 16)                                                            \
            asm volatile("cp.async.ca.shared.global [%0], [%1], 16;"           \
                :: "r"(uS + FMS + (uint32_t)(s) * 256 + (uint32_t)t * 16),     \
                   "l"(mask + (size_t)b * SS + _j0 + t * 4));                  \
        CP_COMMIT();                                                           \
    } while (0)

    float o[8][4];
#pragma unroll
    for (int na = 0; na < 8; na++)
#pragma unroll
        for (int r = 0; r < 4; r++) o[na][r] = 0.f;
    float m0 = -INFINITY, m1 = -INFINITY, l0 = 0.f, l1 = 0.f;
    const float scale2 = 0.125f * 1.44269504089f;  // 1/sqrt(64) * log2(e)

    F_ISSUE(0, 0);

    for (int jt = 0; jt < SS / 64; jt++) {
        const int s = jt & 1;
        CP_WAIT0();
        __syncthreads();
        if (jt + 1 < SS / 64) F_ISSUE(jt + 1, 1 - s);

        const uint32_t uKh = uS + FKV + (uint32_t)(0 * 2 + s) * KTILEB;
        const uint32_t uKl = uS + FKV + (uint32_t)(1 * 2 + s) * KTILEB;
        const uint32_t uVh = uS + FKV + (uint32_t)(2 * 2 + s) * KTILEB;
        const uint32_t uVl = uS + FKV + (uint32_t)(3 * 2 + s) * KTILEB;
        const int* msj = ms + s * 64;

        // ---- GEMM1: S[16 rows x 64 keys] per warp (Q single, K 2-limb) ----
        float sc[8][4];
#pragma unroll
        for (int na = 0; na < 8; na++)
#pragma unroll
            for (int r = 0; r < 4; r++) sc[na][r] = 0.f;

#pragma unroll
        for (int ks = 0; ks < 4; ks++) {
            uint32_t a[4];
            const uint32_t aoff = (uint32_t)((wid * 16 + (lane & 15)) * FSTB
                                             + ks * 32 + (lane >> 4) * 16);
            ldsm_x4(a[0], a[1], a[2], a[3], uQ + aoff);
#pragma unroll
            for (int np = 0; np < 4; np++) {
                const int m = lane >> 3;
                const int row = np * 16 + (m >> 1) * 8 + (lane & 7);
                const uint32_t boff = (uint32_t)(row * FSTB + ks * 32 + (m & 1) * 16);
                uint32_t b0h, b1h, b2h, b3h, b0l, b1l, b2l, b3l;
                ldsm_x4(b0h, b1h, b2h, b3h, uKh + boff);
                ldsm_x4(b0l, b1l, b2l, b3l, uKl + boff);
                const int na0 = np * 2, na1 = np * 2 + 1;
                mma_f16(sc[na0][0], sc[na0][1], sc[na0][2], sc[na0][3],
                        a[0], a[1], a[2], a[3], b0h, b1h);
                mma_f16(sc[na0][0], sc[na0][1], sc[na0][2], sc[na0][3],
                        a[0], a[1], a[2], a[3], b0l, b1l);
                mma_f16(sc[na1][0], sc[na1][1], sc[na1][2], sc[na1][3],
                        a[0], a[1], a[2], a[3], b2h, b3h);
                mma_f16(sc[na1][0], sc[na1][1], sc[na1][2], sc[na1][3],
                        a[0], a[1], a[2], a[3], b2l, b3l);
            }
        }

        // ---- scale (exp2 domain) + mask ----
#pragma unroll
        for (int na = 0; na < 8; na++) {
            const int kc = na * 8 + q * 2;
            const int mk0 = msj[kc], mk1 = msj[kc + 1];
            sc[na][0] = mk0 ? sc[na][0] * scale2 : -1e9f;
            sc[na][1] = mk1 ? sc[na][1] * scale2 : -1e9f;
            sc[na][2] = mk0 ? sc[na][2] * scale2 : -1e9f;
            sc[na][3] = mk1 ? sc[na][3] * scale2 : -1e9f;
        }

        // ---- online softmax in exp2 domain (rows g, g+8; 4 lanes per row) ----
        float mx0 = -INFINITY, mx1 = -INFINITY;
#pragma unroll
        for (int na = 0; na < 8; na++) {
            mx0 = fmaxf(mx0, fmaxf(sc[na][0], sc[na][1]));
            mx1 = fmaxf(mx1, fmaxf(sc[na][2], sc[na][3]));
        }
        mx0 = fmaxf(mx0, __shfl_xor_sync(0xffffffffu, mx0, 1));
        mx0 = fmaxf(mx0, __shfl_xor_sync(0xffffffffu, mx0, 2));
        mx1 = fmaxf(mx1, __shfl_xor_sync(0xffffffffu, mx1, 1));
        mx1 = fmaxf(mx1, __shfl_xor_sync(0xffffffffu, mx1, 2));
        const float mn0 = fmaxf(m0, mx0), mn1 = fmaxf(m1, mx1);
        const float a0 = ex2(m0 - mn0), a1 = ex2(m1 - mn1);
        float sum0 = 0.f, sum1 = 0.f;
#pragma unroll
        for (int na = 0; na < 8; na++) {
            sc[na][0] = ex2(sc[na][0] - mn0); sum0 += sc[na][0];
            sc[na][1] = ex2(sc[na][1] - mn0); sum0 += sc[na][1];
            sc[na][2] = ex2(sc[na][2] - mn1); sum1 += sc[na][2];
            sc[na][3] = ex2(sc[na][3] - mn1); sum1 += sc[na][3];
        }
        sum0 += __shfl_xor_sync(0xffffffffu, sum0, 1);
        sum0 += __shfl_xor_sync(0xffffffffu, sum0, 2);
        sum1 += __shfl_xor_sync(0xffffffffu, sum1, 1);
        sum1 += __shfl_xor_sync(0xffffffffu, sum1, 2);
        l0 = l0 * a0 + sum0;
        l1 = l1 * a1 + sum1;
        m0 = mn0; m1 = mn1;
#pragma unroll
        for (int na = 0; na < 8; na++) {
            o[na][0] *= a0; o[na][1] *= a0;
            o[na][2] *= a1; o[na][3] *= a1;
        }

        // ---- GEMM2: O += P(fp16) * V(fp16 2-limb), V via ldmatrix.x4.trans ----
#pragma unroll
        for (int kk = 0; kk < 4; kk++) {
            uint32_t ph[4];
            ph[0] = packh(sc[2*kk][0],   sc[2*kk][1]);
            ph[1] = packh(sc[2*kk][2],   sc[2*kk][3]);
            ph[2] = packh(sc[2*kk+1][0], sc[2*kk+1][1]);
            ph[3] = packh(sc[2*kk+1][2], sc[2*kk+1][3]);
            const int m = lane >> 3;
#pragma unroll
            for (int np = 0; np < 4; np++) {
                const int row = kk * 16 + (m & 1) * 8 + (lane & 7);
                const int na0 = np * 2, na1 = np * 2 + 1;
                const uint32_t voff = (uint32_t)(row * FSTB + (np * 2 + (m >> 1)) * 16);
                uint32_t v0h, v1h, v2h, v3h, v0l, v1l, v2l, v3l;
                ldsm_x4t(v0h, v1h, v2h, v3h, uVh + voff);
                ldsm_x4t(v0l, v1l, v2l, v3l, uVl + voff);
                mma_f16(o[na0][0], o[na0][1], o[na0][2], o[na0][3],
                        ph[0], ph[1], ph[2], ph[3], v0h, v1h);
                mma_f16(o[na0][0], o[na0][1], o[na0][2], o[na0][3],
                        ph[0], ph[1], ph[2], ph[3], v0l, v1l);
                mma_f16(o[na1][0], o[na1][1], o[na1][2], o[na1][3],
                        ph[0], ph[1], ph[2], ph[3], v2h, v3h);
                mma_f16(o[na1][0], o[na1][1], o[na1][2], o[na1][3],
                        ph[0], ph[1], ph[2], ph[3], v2l, v3l);
            }
        }
    }

    // ---- epilogue: divide by l, write context as single fp16 ----
    const float inv0 = 1.f / l0, inv1 = 1.f / l1;
    const int r0 = i0 + wid * 16 + g;
#pragma unroll
    for (int na = 0; na < 8; na++) {
        const int col = na * 8 + q * 2;
        *(uint32_t*)(C1 + base + (size_t)r0 * DD + col) =
            packh(o[na][0] * inv0, o[na][1] * inv0);
        *(uint32_t*)(C1 + base + (size_t)(r0 + 8) * DD + col) =
            packh(o[na][2] * inv1, o[na][3] * inv1);
    }
}

// ============================================================================
// kernel_launch
// ============================================================================
extern "C" void kernel_launch(void* const* d_in, const int* in_sizes, int n_in,
                              void* d_out, int out_size)
{
    const float* q    = (const float*)d_in[0];
    const float* k    = (const float*)d_in[1];
    const float* v    = (const float*)d_in[2];
    const int*   mask = (const int*)  d_in[3];
    const float* wq   = (const float*)d_in[4];
    const float* bq   = (const float*)d_in[5];
    const float* wk   = (const float*)d_in[6];
    const float* bk   = (const float*)d_in[7];
    const float* wv   = (const float*)d_in[8];
    const float* bv   = (const float*)d_in[9];
    const float* wo   = (const float*)d_in[10];
    const float* bo   = (const float*)d_in[11];
    float* out = (float*)d_out;

    __half *aq, *ak, *av;
    __half *wqh, *wql, *wkh, *wkl, *wvh, *wvl, *woh, *wol;
    __half *q1, *kh, *kl, *vh, *vl, *c1;
    cudaGetSymbolAddress((void**)&aq,  g_Aq);
    cudaGetSymbolAddress((void**)&ak,  g_Ak);
    cudaGetSymbolAddress((void**)&av,  g_Av);
    cudaGetSymbolAddress((void**)&wqh, g_WQh);
    cudaGetSymbolAddress((void**)&wql, g_WQl);
    cudaGetSymbolAddress((void**)&wkh, g_WKh);
    cudaGetSymbolAddress((void**)&wkl, g_WKl);
    cudaGetSymbolAddress((void**)&wvh, g_WVh);
    cudaGetSymbolAddress((void**)&wvl, g_WVl);
    cudaGetSymbolAddress((void**)&woh, g_WOh);
    cudaGetSymbolAddress((void**)&wol, g_WOl);
    cudaGetSymbolAddress((void**)&q1,  g_Q1);
    cudaGetSymbolAddress((void**)&kh,  g_Kh);
    cudaGetSymbolAddress((void**)&kl,  g_Kl);
    cudaGetSymbolAddress((void**)&vh,  g_Vh);
    cudaGetSymbolAddress((void**)&vl,  g_Vl);
    cudaGetSymbolAddress((void**)&c1,  g_C1);

    static bool attr_set = false;
    if (!attr_set) {
        cudaFuncSetAttribute(flash_tc, cudaFuncAttributeMaxDynamicSharedMemorySize,
                             FLASH_SMEM_BYTES);
        cudaFuncSetAttribute(gemm_qkv, cudaFuncAttributeMaxDynamicSharedMemorySize,
                             GS_TOTAL);
        cudaFuncSetAttribute(gemm_o, cudaFuncAttributeMaxDynamicSharedMemorySize,
                             GS_TOTAL);
        attr_set = true;
    }

    const int nA4 = NROWS * DD / 4;   // 1,048,576
    const int nW4 = DD * DD / 4;      //   262,144

    // Input conversions (fp16 single) and weight splits (fp16 2-limb)
    {
        ConvParams cp{};
        cp.x[0] = q; cp.y[0] = aq;
        cp.x[1] = k; cp.y[1] = ak;
        cp.x[2] = v; cp.y[2] = av;
        conv_half_multi<<<3 * nA4 / 256, 256>>>(cp, nA4);
    }
    {
        SplitHParams sp{};
        sp.x[0] = wq; sp.hi[0] = wqh; sp.lo[0] = wql;
        sp.x[1] = wk; sp.hi[1] = wkh; sp.lo[1] = wkl;
        sp.x[2] = wv; sp.hi[2] = wvh; sp.lo[2] = wvl;
        sp.x[3] = wo; sp.hi[3] = woh; sp.lo[3] = wol;
        split_half_multi<<<4 * nW4 / 256, 256>>>(sp, nW4);
    }

    // Batched Q/K/V projections: z=0 Q (single out), z=1 K, z=2 V (2-limb out)
    {
        QKVParams p{};
        p.A[0] = aq; p.Wh[0] = wqh; p.Wl[0] = wql; p.bias[0] = bq;
        p.C1[0] = q1; p.C2h[0] = nullptr; p.C2l[0] = nullptr;
        p.A[1] = ak; p.Wh[1] = wkh; p.Wl[1] = wkl; p.bias[1] = bk;
        p.C1[1] = nullptr; p.C2h[1] = kh; p.C2l[1] = kl;
        p.A[2] = av; p.Wh[2] = wvh; p.Wl[2] = wvl; p.bias[2] = bv;
        p.C1[2] = nullptr; p.C2h[2] = vh; p.C2l[2] = vl;
        dim3 tgrid(DD / 128, NROWS / 128, 3);   // (8, 32, 3) = 768 CTAs
        gemm_qkv<<<tgrid, 256, GS_TOTAL>>>(p);
    }

    // Attention (writes single-fp16 context)
    dim3 fgrid(SS / 128, HH, BB);        // (16, 16, 2)
    flash_tc<<<fgrid, 256, FLASH_SMEM_BYTES>>>(q1, kh, kl, vh, vl, mask, c1);

    // Output projection (fp32 out)
    dim3 ogrid(DD / 128, NROWS / 128);   // (8, 32)
    gemm_o<<<ogrid, 256, GS_TOTAL>>>(c1, woh, wol, bo, out);
}

// round 14
// speedup vs baseline: 1.4079x; 1.0146x over previous
#include <cuda_runtime.h>
#include <cuda_bf16.h>
#include <cuda_fp16.h>
#include <math.h>
#include <stdint.h>

// Problem constants
#define BB   2
#define SS   2048
#define DD   1024
#define HH   16
#define DK   64
#define NROWS (BB*SS)   // 4096

// Scratch (allocation-free rule: device globals) — fp16 scheme:
// A-operands single fp16; B-operands 2-limb fp16.
__device__ __half g_Aq[NROWS*DD];
__device__ __half g_Ak[NROWS*DD];
__device__ __half g_Av[NROWS*DD];
__device__ __half g_WQh[DD*DD];
__device__ __half g_WQl[DD*DD];
__device__ __half g_WKh[DD*DD];
__device__ __half g_WKl[DD*DD];
__device__ __half g_WVh[DD*DD];
__device__ __half g_WVl[DD*DD];
__device__ __half g_WOh[DD*DD];
__device__ __half g_WOl[DD*DD];
__device__ __half g_Q1[NROWS*DD];    // Q projection, single fp16 (A of GEMM1)
__device__ __half g_Kh[NROWS*DD];    // K projection, 2-limb (B of GEMM1)
__device__ __half g_Kl[NROWS*DD];
__device__ __half g_Vh[NROWS*DD];    // V projection, 2-limb (B of GEMM2)
__device__ __half g_Vl[NROWS*DD];
__device__ __half g_C1[NROWS*DD];    // context, single fp16 (A of O-proj)

// ---------------------------------------------------------------------------
// Base-ISA helpers: ldmatrix + mma.sync + cp.async (all compile for sm_103)
// ---------------------------------------------------------------------------
__device__ __forceinline__ uint32_t smem_u32(const void* p) {
    uint32_t a;
    asm("{ .reg .u64 t; cvta.to.shared.u64 t, %1; cvt.u32.u64 %0, t; }" : "=r"(a) : "l"(p));
    return a;
}
__device__ __forceinline__ void ldsm_x4(uint32_t& r0, uint32_t& r1, uint32_t& r2,
                                        uint32_t& r3, uint32_t addr) {
    asm volatile("ldmatrix.sync.aligned.m8n8.x4.shared.b16 {%0,%1,%2,%3}, [%4];"
                 : "=r"(r0), "=r"(r1), "=r"(r2), "=r"(r3) : "r"(addr));
}
__device__ __forceinline__ void ldsm_x4t(uint32_t& r0, uint32_t& r1, uint32_t& r2,
                                         uint32_t& r3, uint32_t addr) {
    asm volatile("ldmatrix.sync.aligned.m8n8.x4.trans.shared.b16 {%0,%1,%2,%3}, [%4];"
                 : "=r"(r0), "=r"(r1), "=r"(r2), "=r"(r3) : "r"(addr));
}
__device__ __forceinline__ void mma_f16(float& c0, float& c1, float& c2, float& c3,
                                        uint32_t a0, uint32_t a1, uint32_t a2, uint32_t a3,
                                        uint32_t b0, uint32_t b1) {
    asm volatile("mma.sync.aligned.m16n8k16.row.col.f32.f16.f16.f32 "
                 "{%0,%1,%2,%3}, {%4,%5,%6,%7}, {%8,%9}, {%0,%1,%2,%3};"
                 : "+f"(c0), "+f"(c1), "+f"(c2), "+f"(c3)
                 : "r"(a0), "r"(a1), "r"(a2), "r"(a3), "r"(b0), "r"(b1));
}
__device__ __forceinline__ void cp16(uint32_t saddr, const void* g) {
    asm volatile("cp.async.cg.shared.global [%0], [%1], 16;" :: "r"(saddr), "l"(g));
}
#define CP_COMMIT() asm volatile("cp.async.commit_group;" ::: "memory")
#define CP_WAIT0()  asm volatile("cp.async.wait_group 0;"  ::: "memory")

__device__ __forceinline__ float ex2(float x) {
    float r; asm("ex2.approx.f32 %0, %1;" : "=f"(r) : "f"(x)); return r;
}
// f16x2 exp2: two fp16 exponentials in one MUFU op
__device__ __forceinline__ uint32_t h2ex2(uint32_t x) {
    uint32_t r; asm("ex2.approx.f16x2 %0, %1;" : "=r"(r) : "r"(x)); return r;
}
// pack two fp32 into f16x2 (lo half = first arg)
__device__ __forceinline__ uint32_t packh(float lo, float hi) {
    uint32_t r;
    asm("cvt.rn.f16x2.f32 %0, %1, %2;" : "=r"(r) : "f"(hi), "f"(lo));
    return r;
}
// split a pair of fp32 into f16x2 hi and f16x2 lo (packed uint32)
__device__ __forceinline__ void split2h(float a, float b, uint32_t& hi, uint32_t& lo) {
    __half2 h = __float22half2_rn(make_float2(a, b));
    float2 hf = __half22float2(h);
    __half2 l = __float22half2_rn(make_float2(a - hf.x, b - hf.y));
    hi = *(uint32_t*)&h;
    lo = *(uint32_t*)&l;
}

// ============================================================================
// fp32 -> fp16 single conversion (3 inputs, one launch)
// ============================================================================
struct ConvParams {
    const float* x[3];
    __half* y[3];
};

__global__ __launch_bounds__(256)
void conv_half_multi(ConvParams p, int n4_each)
{
    int gi = blockIdx.x * blockDim.x + threadIdx.x;
    const int which = gi / n4_each;
    const int i = gi - which * n4_each;
    float4 v = ((const float4*)p.x[which])[i];
    uint2 o;
    o.x = packh(v.x, v.y);
    o.y = packh(v.z, v.w);
    ((uint2*)p.y[which])[i] = o;
}

// fp32 -> (fp16 hi, fp16 lo) split (4 weights, one launch)
struct SplitHParams {
    const float* x[4];
    __half* hi[4];
    __half* lo[4];
};

__global__ __launch_bounds__(256)
void split_half_multi(SplitHParams p, int n4_each)
{
    int gi = blockIdx.x * blockDim.x + threadIdx.x;
    const int which = gi / n4_each;
    const int i = gi - which * n4_each;
    float4 v = ((const float4*)p.x[which])[i];
    uint2 hh, ll;
    split2h(v.x, v.y, hh.x, ll.x);
    split2h(v.z, v.w, hh.y, ll.y);
    ((uint2*)p.hi[which])[i] = hh;
    ((uint2*)p.lo[which])[i] = ll;
}

// ============================================================================
// Tensor-core GEMM, cp.async 2-stage pipelined, fp16 asymmetric limbs:
//   C[M,N] = A[M,K] * W[N,K]^T + bias[N],  A single fp16, W 2-limb fp16.
// Block tile 128x64, K-chunk 32. 8 warps, warp tile 64x16. 2 mma per atom.
// 3 CTAs/SM target (smem 41KB, ~70 regs). outMode: 0 fp32; 1 fp16; 2 2-limb.
// ============================================================================
#define TBK 32
#define TROW 40                  // smem row stride (fp16): 80B, conflict-free ldmatrix
#define GA_BYTES (128*TROW*2)    // 10240
#define GB_BYTES (64*TROW*2)     // 5120
#define GSTAGE (GA_BYTES + 2*GB_BYTES)   // 20480
#define GS_TOTAL (2*GSTAGE)              // 40960

struct QKVParams {
    const __half* A[3];
    const __half* Wh[3];
    const __half* Wl[3];
    const float* bias[3];
    __half* C1[3];
    __half* C2h[3];
    __half* C2l[3];
};

__device__ __forceinline__ void gemm_body(
    const __half* __restrict__ A,
    const __half* __restrict__ Bh, const __half* __restrict__ Bl,
    const float* __restrict__ bias, float* __restrict__ C,
    __half* __restrict__ C1, __half* __restrict__ C2h, __half* __restrict__ C2l,
    int N, int K, int outMode, char* dynsm)
{
    const uint32_t uS = smem_u32(dynsm);
    const int t    = threadIdx.x;
    const int wid  = t >> 5;
    const int lane = t & 31;
    const int m0 = blockIdx.y * 128;
    const int n0 = blockIdx.x * 64;
    const int wm = (wid & 1) * 64;
    const int wn = (wid >> 1) * 16;
    const int nchunk = K / TBK;

    const int lrow0 = t >> 2;            // 0..63
    const int lcc   = (t & 3) * 8;       // fp16 col: 0,8,16,24

#define G_ISSUE(c, s) do {                                                     \
        const int _k0 = (c) * TBK;                                             \
        const uint32_t _b = uS + (uint32_t)(s) * GSTAGE;                       \
        const uint32_t _so = (uint32_t)((lrow0 * TROW + lcc) * 2);             \
        cp16(_b + _so, A + (size_t)(m0 + lrow0) * K + _k0 + lcc);              \
        cp16(_b + (uint32_t)(64 * TROW * 2) + _so,                             \
             A + (size_t)(m0 + 64 + lrow0) * K + _k0 + lcc);                   \
        cp16(_b + GA_BYTES + _so,                                              \
             Bh + (size_t)(n0 + lrow0) * K + _k0 + lcc);                       \
        cp16(_b + GA_BYTES + GB_BYTES + _so,                                   \
             Bl + (size_t)(n0 + lrow0) * K + _k0 + lcc);                       \
        CP_COMMIT();                                                           \
    } while (0)

    float acc[4][2][4];
#pragma unroll
    for (int i = 0; i < 4; i++)
#pragma unroll
        for (int j = 0; j < 2; j++)
#pragma unroll
            for (int r = 0; r < 4; r++) acc[i][j][r] = 0.f;

    G_ISSUE(0, 0);

    for (int c = 0; c < nchunk; c++) {
        const int s = c & 1;
        CP_WAIT0();
        __syncthreads();   // orders prev-iter reads of the other stage vs new writes
        if (c + 1 < nchunk) G_ISSUE(c + 1, 1 - s);

        const uint32_t uA  = uS + (uint32_t)(s) * GSTAGE;
        const uint32_t uBh = uA + GA_BYTES;
        const uint32_t uBl = uBh + GB_BYTES;

#pragma unroll
        for (int ks = 0; ks < 2; ks++) {
            uint32_t a[4][4];
#pragma unroll
            for (int ma = 0; ma < 4; ma++) {
                const int row = wm + ma * 16 + (lane & 15);
                const uint32_t off = (uint32_t)(row * TROW * 2 + ks * 32 + (lane >> 4) * 16);
                ldsm_x4(a[ma][0], a[ma][1], a[ma][2], a[ma][3], uA + off);
            }
            uint32_t bh[2][2], bl[2][2];
            {
                const int m = lane >> 3;
                const int row = wn + (m >> 1) * 8 + (lane & 7);
                const uint32_t off = (uint32_t)(row * TROW * 2 + ks * 32 + (m & 1) * 16);
                ldsm_x4(bh[0][0], bh[0][1], bh[1][0], bh[1][1], uBh + off);
                ldsm_x4(bl[0][0], bl[0][1], bl[1][0], bl[1][1], uBl + off);
            }
#pragma unroll
            for (int ma = 0; ma < 4; ma++)
#pragma unroll
                for (int na = 0; na < 2; na++) {
                    float* cc = acc[ma][na];
                    mma_f16(cc[0], cc[1], cc[2], cc[3],
                            a[ma][0], a[ma][1], a[ma][2], a[ma][3],
                            bh[na][0], bh[na][1]);
                    mma_f16(cc[0], cc[1], cc[2], cc[3],
                            a[ma][0], a[ma][1], a[ma][2], a[ma][3],
                            bl[na][0], bl[na][1]);
                }
        }
    }

    const int g = lane >> 2;
    const int q = lane & 3;
#pragma unroll
    for (int ma = 0; ma < 4; ma++) {
#pragma unroll
        for (int na = 0; na < 2; na++) {
            const int col = n0 + wn + na * 8 + q * 2;
            const float b0 = bias[col], b1 = bias[col + 1];
            const int r0 = m0 + wm + ma * 16 + g;
            const float v00 = acc[ma][na][0] + b0, v01 = acc[ma][na][1] + b1;
            const float v10 = acc[ma][na][2] + b0, v11 = acc[ma][na][3] + b1;
            if (outMode == 1) {
                *(uint32_t*)(C1 + (size_t)r0 * N + col)       = packh(v00, v01);
                *(uint32_t*)(C1 + (size_t)(r0 + 8) * N + col) = packh(v10, v11);
            } else if (outMode == 2) {
                uint32_t h, l;
                split2h(v00, v01, h, l);
                *(uint32_t*)(C2h + (size_t)r0 * N + col) = h;
                *(uint32_t*)(C2l + (size_t)r0 * N + col) = l;
                split2h(v10, v11, h, l);
                *(uint32_t*)(C2h + (size_t)(r0 + 8) * N + col) = h;
                *(uint32_t*)(C2l + (size_t)(r0 + 8) * N + col) = l;
            } else {
                float* d0 = C + (size_t)r0 * N + col;
                d0[0] = v00; d0[1] = v01;
                float* d1 = C + (size_t)(r0 + 8) * N + col;
                d1[0] = v10; d1[1] = v11;
            }
        }
    }
#undef G_ISSUE
}

__global__ __launch_bounds__(256)
void gemm_qkv(QKVParams p)
{
    extern __shared__ char dynsm[];
    const int z = blockIdx.z;
    gemm_body(p.A[z], p.Wh[z], p.Wl[z], p.bias[z],
              nullptr, p.C1[z], p.C2h[z], p.C2l[z], DD, DD,
              (z == 0) ? 1 : 2, dynsm);
}

__global__ __launch_bounds__(256)
void gemm_o(const __half* __restrict__ A,
            const __half* __restrict__ Bh, const __half* __restrict__ Bl,
            const float* __restrict__ bias, float* __restrict__ C)
{
    extern __shared__ char dynsm[];
    gemm_body(A, Bh, Bl, bias, C, nullptr, nullptr, nullptr, DD, DD, 0, dynsm);
}

// ============================================================================
// Flash attention on mma.sync fp16, cp.async double-buffered K/V.
// GEMM1: Q single fp16 x K 2-limb. GEMM2: P fp16 x V 2-limb.
// Softmax: exp2 computed in f16x2 (one MUFU per 2 elements), P fragments
// produced mma-ready. Block: 128 q-rows, 64-key tiles, 8 warps.
// ============================================================================
#define FST 72                        // smem row stride (fp16): 144 B
#define FSTB (FST*2)
#define QTILEB (128*FSTB)             // 18432 B (single Q array)
#define KTILEB (64*FSTB)              // 9216 B per K/V array per stage
#define FKV QTILEB
#define FMS (FKV + 8*KTILEB)          // int ms[2][64]
#define FLASH_SMEM_BYTES (FMS + 512)  // 92672 B

__global__ __launch_bounds__(256, 2)
void flash_tc(const __half* __restrict__ Q1,
              const __half* __restrict__ Kh, const __half* __restrict__ Kl,
              const __half* __restrict__ Vh, const __half* __restrict__ Vl,
              const int* __restrict__ mask,
              __half* __restrict__ C1)
{
    extern __shared__ char dynsm[];
    const uint32_t uS = smem_u32(dynsm);
    const uint32_t uQ = uS;
    int* ms = (int*)(dynsm + FMS);

    const int t    = threadIdx.x;
    const int wid  = t >> 5;
    const int lane = t & 31;
    const int g    = lane >> 2;
    const int q    = lane & 3;
    const int i0   = blockIdx.x * 128;
    const int h    = blockIdx.y;
    const int b    = blockIdx.z;
    const size_t base = (size_t)b * SS * DD + (size_t)h * DK;

    // Load Q tile (plain stores; first loop-top sync publishes them)
    {
        __half* sQ = (__half*)dynsm;
#pragma unroll
        for (int p = 0; p < 4; p++) {
            const int idx = t + p * 256;
            const int row = idx >> 3;
            const int c   = (idx & 7) * 8;
            *(uint4*)(sQ + row * FST + c) =
                *(const uint4*)(Q1 + base + (size_t)(i0 + row) * DD + c);
        }
    }

    const int lrow = t >> 3;         // 0..31
    const int lcc  = (t & 7) * 8;    // fp16 col

#define F_ISSUE(jt, s) do {                                                    \
        const int _j0 = (jt) * 64;                                             \
        _Pragma("unroll")                                                      \
        for (int _p = 0; _p < 2; _p++) {                                       \
            const int _row = lrow + _p * 32;                                   \
            const size_t _gk = base + (size_t)(_j0 + _row) * DD + lcc;         \
            const uint32_t _so = (uint32_t)(_row * FSTB + lcc * 2);            \
            cp16(uS + FKV + (uint32_t)(0 * 2 + (s)) * KTILEB + _so, Kh + _gk); \
            cp16(uS + FKV + (uint32_t)(1 * 2 + (s)) * KTILEB + _so, Kl + _gk); \
            cp16(uS + FKV + (uint32_t)(2 * 2 + (s)) * KTILEB + _so, Vh + _gk); \
            cp16(uS + FKV + (uint32_t)(3 * 2 + (s)) * KTILEB + _so, Vl + _gk); \
        }                                                                      \
        if (t < 16)                                                            \
            asm volatile("cp.async.ca.shared.global [%0], [%1], 16;"           \
                :: "r"(uS + FMS + (uint32_t)(s) * 256 + (uint32_t)t * 16),     \
                   "l"(mask + (size_t)b * SS + _j0 + t * 4));                  \
        CP_COMMIT();                                                           \
    } while (0)

    float o[8][4];
#pragma unroll
    for (int na = 0; na < 8; na++)
#pragma unroll
        for (int r = 0; r < 4; r++) o[na][r] = 0.f;
    float m0 = -INFINITY, m1 = -INFINITY, l0 = 0.f, l1 = 0.f;
    const float scale2 = 0.125f * 1.44269504089f;  // 1/sqrt(64) * log2(e)

    F_ISSUE(0, 0);

    for (int jt = 0; jt < SS / 64; jt++) {
        const int s = jt & 1;
        CP_WAIT0();
        __syncthreads();
        if (jt + 1 < SS / 64) F_ISSUE(jt + 1, 1 - s);

        const uint32_t uKh = uS + FKV + (uint32_t)(0 * 2 + s) * KTILEB;
        const uint32_t uKl = uS + FKV + (uint32_t)(1 * 2 + s) * KTILEB;
        const uint32_t uVh = uS + FKV + (uint32_t)(2 * 2 + s) * KTILEB;
        const uint32_t uVl = uS + FKV + (uint32_t)(3 * 2 + s) * KTILEB;
        const int* msj = ms + s * 64;

        // ---- GEMM1: S[16 rows x 64 keys] per warp (Q single, K 2-limb) ----
        float sc[8][4];
#pragma unroll
        for (int na = 0; na < 8; na++)
#pragma unroll
            for (int r = 0; r < 4; r++) sc[na][r] = 0.f;

#pragma unroll
        for (int ks = 0; ks < 4; ks++) {
            uint32_t a[4];
            const uint32_t aoff = (uint32_t)((wid * 16 + (lane & 15)) * FSTB
                                             + ks * 32 + (lane >> 4) * 16);
            ldsm_x4(a[0], a[1], a[2], a[3], uQ + aoff);
#pragma unroll
            for (int np = 0; np < 4; np++) {
                const int m = lane >> 3;
                const int row = np * 16 + (m >> 1) * 8 + (lane & 7);
                const uint32_t boff = (uint32_t)(row * FSTB + ks * 32 + (m & 1) * 16);
                uint32_t b0h, b1h, b2h, b3h, b0l, b1l, b2l, b3l;
                ldsm_x4(b0h, b1h, b2h, b3h, uKh + boff);
                ldsm_x4(b0l, b1l, b2l, b3l, uKl + boff);
                const int na0 = np * 2, na1 = np * 2 + 1;
                mma_f16(sc[na0][0], sc[na0][1], sc[na0][2], sc[na0][3],
                        a[0], a[1], a[2], a[3], b0h, b1h);
                mma_f16(sc[na0][0], sc[na0][1], sc[na0][2], sc[na0][3],
                        a[0], a[1], a[2], a[3], b0l, b1l);
                mma_f16(sc[na1][0], sc[na1][1], sc[na1][2], sc[na1][3],
                        a[0], a[1], a[2], a[3], b2h, b3h);
                mma_f16(sc[na1][0], sc[na1][1], sc[na1][2], sc[na1][3],
                        a[0], a[1], a[2], a[3], b2l, b3l);
            }
        }

        // ---- scale (exp2 domain) + mask ----
#pragma unroll
        for (int na = 0; na < 8; na++) {
            const int kc = na * 8 + q * 2;
            const int mk0 = msj[kc], mk1 = msj[kc + 1];
            sc[na][0] = mk0 ? sc[na][0] * scale2 : -1e9f;
            sc[na][1] = mk1 ? sc[na][1] * scale2 : -1e9f;
            sc[na][2] = mk0 ? sc[na][2] * scale2 : -1e9f;
            sc[na][3] = mk1 ? sc[na][3] * scale2 : -1e9f;
        }

        // ---- online softmax (rows g, g+8; 4 lanes per row) ----
        float mx0 = -INFINITY, mx1 = -INFINITY;
#pragma unroll
        for (int na = 0; na < 8; na++) {
            mx0 = fmaxf(mx0, fmaxf(sc[na][0], sc[na][1]));
            mx1 = fmaxf(mx1, fmaxf(sc[na][2], sc[na][3]));
        }
        mx0 = fmaxf(mx0, __shfl_xor_sync(0xffffffffu, mx0, 1));
        mx0 = fmaxf(mx0, __shfl_xor_sync(0xffffffffu, mx0, 2));
        mx1 = fmaxf(mx1, __shfl_xor_sync(0xffffffffu, mx1, 1));
        mx1 = fmaxf(mx1, __shfl_xor_sync(0xffffffffu, mx1, 2));
        const float mn0 = fmaxf(m0, mx0), mn1 = fmaxf(m1, mx1);
        const float a0 = ex2(m0 - mn0), a1 = ex2(m1 - mn1);

        // P = exp2(sc - mn) computed in f16x2, fragments mma-ready:
        // pA[na] = rows g pair (a0-slot), pB[na] = rows g+8 pair (a1-slot)
        uint32_t pA[8], pB[8];
        float sum0 = 0.f, sum1 = 0.f;
#pragma unroll
        for (int na = 0; na < 8; na++) {
            pA[na] = h2ex2(packh(sc[na][0] - mn0, sc[na][1] - mn0));
            pB[na] = h2ex2(packh(sc[na][2] - mn1, sc[na][3] - mn1));
            float2 f0 = __half22float2(*(__half2*)&pA[na]);
            float2 f1 = __half22float2(*(__half2*)&pB[na]);
            sum0 += f0.x + f0.y;
            sum1 += f1.x + f1.y;
        }
        sum0 += __shfl_xor_sync(0xffffffffu, sum0, 1);
        sum0 += __shfl_xor_sync(0xffffffffu, sum0, 2);
        sum1 += __shfl_xor_sync(0xffffffffu, sum1, 1);
        sum1 += __shfl_xor_sync(0xffffffffu, sum1, 2);
        l0 = l0 * a0 + sum0;
        l1 = l1 * a1 + sum1;
        m0 = mn0; m1 = mn1;
#pragma unroll
        for (int na = 0; na < 8; na++) {
            o[na][0] *= a0; o[na][1] *= a0;
            o[na][2] *= a1; o[na][3] *= a1;
        }

        // ---- GEMM2: O += P(fp16) * V(fp16 2-limb), V via ldmatrix.x4.trans ----
#pragma unroll
        for (int kk = 0; kk < 4; kk++) {
            const uint32_t ph0 = pA[2*kk],   ph1 = pB[2*kk];
            const uint32_t ph2 = pA[2*kk+1], ph3 = pB[2*kk+1];
            const int m = lane >> 3;
#pragma unroll
            for (int np = 0; np < 4; np++) {
                const int row = kk * 16 + (m & 1) * 8 + (lane & 7);
                const int na0 = np * 2, na1 = np * 2 + 1;
                const uint32_t voff = (uint32_t)(row * FSTB + (np * 2 + (m >> 1)) * 16);
                uint32_t v0h, v1h, v2h, v3h, v0l, v1l, v2l, v3l;
                ldsm_x4t(v0h, v1h, v2h, v3h, uVh + voff);
                ldsm_x4t(v0l, v1l, v2l, v3l, uVl + voff);
                mma_f16(o[na0][0], o[na0][1], o[na0][2], o[na0][3],
                        ph0, ph1, ph2, ph3, v0h, v1h);
                mma_f16(o[na0][0], o[na0][1], o[na0][2], o[na0][3],
                        ph0, ph1, ph2, ph3, v0l, v1l);
                mma_f16(o[na1][0], o[na1][1], o[na1][2], o[na1][3],
                        ph0, ph1, ph2, ph3, v2h, v3h);
                mma_f16(o[na1][0], o[na1][1], o[na1][2], o[na1][3],
                        ph0, ph1, ph2, ph3, v2l, v3l);
            }
        }
    }

    // ---- epilogue: divide by l, write context as single fp16 ----
    const float inv0 = 1.f / l0, inv1 = 1.f / l1;
    const int r0 = i0 + wid * 16 + g;
#pragma unroll
    for (int na = 0; na < 8; na++) {
        const int col = na * 8 + q * 2;
        *(uint32_t*)(C1 + base + (size_t)r0 * DD + col) =
            packh(o[na][0] * inv0, o[na][1] * inv0);
        *(uint32_t*)(C1 + base + (size_t)(r0 + 8) * DD + col) =
            packh(o[na][2] * inv1, o[na][3] * inv1);
    }
}

// ============================================================================
// kernel_launch
// ============================================================================
extern "C" void kernel_launch(void* const* d_in, const int* in_sizes, int n_in,
                              void* d_out, int out_size)
{
    const float* q    = (const float*)d_in[0];
    const float* k    = (const float*)d_in[1];
    const float* v    = (const float*)d_in[2];
    const int*   mask = (const int*)  d_in[3];
    const float* wq   = (const float*)d_in[4];
    const float* bq   = (const float*)d_in[5];
    const float* wk   = (const float*)d_in[6];
    const float* bk   = (const float*)d_in[7];
    const float* wv   = (const float*)d_in[8];
    const float* bv   = (const float*)d_in[9];
    const float* wo   = (const float*)d_in[10];
    const float* bo   = (const float*)d_in[11];
    float* out = (float*)d_out;

    __half *aq, *ak, *av;
    __half *wqh, *wql, *wkh, *wkl, *wvh, *wvl, *woh, *wol;
    __half *q1, *kh, *kl, *vh, *vl, *c1;
    cudaGetSymbolAddress((void**)&aq,  g_Aq);
    cudaGetSymbolAddress((void**)&ak,  g_Ak);
    cudaGetSymbolAddress((void**)&av,  g_Av);
    cudaGetSymbolAddress((void**)&wqh, g_WQh);
    cudaGetSymbolAddress((void**)&wql, g_WQl);
    cudaGetSymbolAddress((void**)&wkh, g_WKh);
    cudaGetSymbolAddress((void**)&wkl, g_WKl);
    cudaGetSymbolAddress((void**)&wvh, g_WVh);
    cudaGetSymbolAddress((void**)&wvl, g_WVl);
    cudaGetSymbolAddress((void**)&woh, g_WOh);
    cudaGetSymbolAddress((void**)&wol, g_WOl);
    cudaGetSymbolAddress((void**)&q1,  g_Q1);
    cudaGetSymbolAddress((void**)&kh,  g_Kh);
    cudaGetSymbolAddress((void**)&kl,  g_Kl);
    cudaGetSymbolAddress((void**)&vh,  g_Vh);
    cudaGetSymbolAddress((void**)&vl,  g_Vl);
    cudaGetSymbolAddress((void**)&c1,  g_C1);

    static bool attr_set = false;
    if (!attr_set) {
        cudaFuncSetAttribute(flash_tc, cudaFuncAttributeMaxDynamicSharedMemorySize,
                             FLASH_SMEM_BYTES);
        cudaFuncSetAttribute(gemm_qkv, cudaFuncAttributeMaxDynamicSharedMemorySize,
                             GS_TOTAL);
        cudaFuncSetAttribute(gemm_o, cudaFuncAttributeMaxDynamicSharedMemorySize,
                             GS_TOTAL);
        attr_set = true;
    }

    const int nA4 = NROWS * DD / 4;   // 1,048,576
    const int nW4 = DD * DD / 4;      //   262,144

    // Input conversions (fp16 single) and weight splits (fp16 2-limb)
    {
        ConvParams cp{};
        cp.x[0] = q; cp.y[0] = aq;
        cp.x[1] = k; cp.y[1] = ak;
        cp.x[2] = v; cp.y[2] = av;
        conv_half_multi<<<3 * nA4 / 256, 256>>>(cp, nA4);
    }
    {
        SplitHParams sp{};
        sp.x[0] = wq; sp.hi[0] = wqh; sp.lo[0] = wql;
        sp.x[1] = wk; sp.hi[1] = wkh; sp.lo[1] = wkl;
        sp.x[2] = wv; sp.hi[2] = wvh; sp.lo[2] = wvl;
        sp.x[3] = wo; sp.hi[3] = woh; sp.lo[3] = wol;
        split_half_multi<<<4 * nW4 / 256, 256>>>(sp, nW4);
    }

    // Batched Q/K/V projections: z=0 Q (single out), z=1 K, z=2 V (2-limb out)
    {
        QKVParams p{};
        p.A[0] = aq; p.Wh[0] = wqh; p.Wl[0] = wql; p.bias[0] = bq;
        p.C1[0] = q1; p.C2h[0] = nullptr; p.C2l[0] = nullptr;
        p.A[1] = ak; p.Wh[1] = wkh; p.Wl[1] = wkl; p.bias[1] = bk;
        p.C1[1] = nullptr; p.C2h[1] = kh; p.C2l[1] = kl;
        p.A[2] = av; p.Wh[2] = wvh; p.Wl[2] = wvl; p.bias[2] = bv;
        p.C1[2] = nullptr; p.C2h[2] = vh; p.C2l[2] = vl;
        dim3 tgrid(DD / 64, NROWS / 128, 3);   // (16, 32, 3) = 1536 CTAs
        gemm_qkv<<<tgrid, 256, GS_TOTAL>>>(p);
    }

    // Attention (writes single-fp16 context)
    dim3 fgrid(SS / 128, HH, BB);        // (16, 16, 2)
    flash_tc<<<fgrid, 256, FLASH_SMEM_BYTES>>>(q1, kh, kl, vh, vl, mask, c1);

    // Output projection (fp32 out)
    dim3 ogrid(DD / 64, NROWS / 128);    // (16, 32) = 512 CTAs
    gemm_o<<<ogrid, 256, GS_TOTAL>>>(c1, woh, wol, bo, out);
}

// round 16
// speedup vs baseline: 1.4485x; 1.0288x over previous
#include <cuda_runtime.h>
#include <cuda_bf16.h>
#include <cuda_fp16.h>
#include <math.h>
#include <stdint.h>

// Problem constants
#define BB   2
#define SS   2048
#define DD   1024
#define HH   16
#define DK   64
#define NROWS (BB*SS)   // 4096

// Scratch (allocation-free rule: device globals) — fp16 scheme:
// A-operands single fp16; B-operands 2-limb fp16.
__device__ __half g_Aq[NROWS*DD];
__device__ __half g_Ak[NROWS*DD];
__device__ __half g_Av[NROWS*DD];
__device__ __half g_WQh[DD*DD];
__device__ __half g_WQl[DD*DD];
__device__ __half g_WKh[DD*DD];
__device__ __half g_WKl[DD*DD];
__device__ __half g_WVh[DD*DD];
__device__ __half g_WVl[DD*DD];
__device__ __half g_WOh[DD*DD];
__device__ __half g_WOl[DD*DD];
__device__ __half g_Q1[NROWS*DD];    // Q projection, single fp16 (A of GEMM1)
__device__ __half g_Kh[NROWS*DD];    // K projection, 2-limb (B of GEMM1)
__device__ __half g_Kl[NROWS*DD];
__device__ __half g_Vh[NROWS*DD];    // V projection, 2-limb (B of GEMM2)
__device__ __half g_Vl[NROWS*DD];
__device__ __half g_C1[NROWS*DD];    // context, single fp16 (A of O-proj)

// ---------------------------------------------------------------------------
// Base-ISA helpers: ldmatrix + mma.sync + cp.async (all compile for sm_103)
// ---------------------------------------------------------------------------
__device__ __forceinline__ uint32_t smem_u32(const void* p) {
    uint32_t a;
    asm("{ .reg .u64 t; cvta.to.shared.u64 t, %1; cvt.u32.u64 %0, t; }" : "=r"(a) : "l"(p));
    return a;
}
__device__ __forceinline__ void ldsm_x4(uint32_t& r0, uint32_t& r1, uint32_t& r2,
                                        uint32_t& r3, uint32_t addr) {
    asm volatile("ldmatrix.sync.aligned.m8n8.x4.shared.b16 {%0,%1,%2,%3}, [%4];"
                 : "=r"(r0), "=r"(r1), "=r"(r2), "=r"(r3) : "r"(addr));
}
__device__ __forceinline__ void ldsm_x4t(uint32_t& r0, uint32_t& r1, uint32_t& r2,
                                         uint32_t& r3, uint32_t addr) {
    asm volatile("ldmatrix.sync.aligned.m8n8.x4.trans.shared.b16 {%0,%1,%2,%3}, [%4];"
                 : "=r"(r0), "=r"(r1), "=r"(r2), "=r"(r3) : "r"(addr));
}
__device__ __forceinline__ void mma_f16(float& c0, float& c1, float& c2, float& c3,
                                        uint32_t a0, uint32_t a1, uint32_t a2, uint32_t a3,
                                        uint32_t b0, uint32_t b1) {
    asm volatile("mma.sync.aligned.m16n8k16.row.col.f32.f16.f16.f32 "
                 "{%0,%1,%2,%3}, {%4,%5,%6,%7}, {%8,%9}, {%0,%1,%2,%3};"
                 : "+f"(c0), "+f"(c1), "+f"(c2), "+f"(c3)
                 : "r"(a0), "r"(a1), "r"(a2), "r"(a3), "r"(b0), "r"(b1));
}
__device__ __forceinline__ void cp16(uint32_t saddr, const void* g) {
    asm volatile("cp.async.cg.shared.global [%0], [%1], 16;" :: "r"(saddr), "l"(g));
}
#define CP_COMMIT() asm volatile("cp.async.commit_group;" ::: "memory")
#define CP_WAIT0()  asm volatile("cp.async.wait_group 0;"  ::: "memory")

__device__ __forceinline__ float ex2(float x) {
    float r; asm("ex2.approx.f32 %0, %1;" : "=f"(r) : "f"(x)); return r;
}
// f16x2 exp2: two fp16 exponentials in one MUFU op
__device__ __forceinline__ uint32_t h2ex2(uint32_t x) {
    uint32_t r; asm("ex2.approx.f16x2 %0, %1;" : "=r"(r) : "r"(x)); return r;
}
// pack two fp32 into f16x2 (lo half = first arg)
__device__ __forceinline__ uint32_t packh(float lo, float hi) {
    uint32_t r;
    asm("cvt.rn.f16x2.f32 %0, %1, %2;" : "=r"(r) : "f"(hi), "f"(lo));
    return r;
}
// split a pair of fp32 into f16x2 hi and f16x2 lo (packed uint32)
__device__ __forceinline__ void split2h(float a, float b, uint32_t& hi, uint32_t& lo) {
    __half2 h = __float22half2_rn(make_float2(a, b));
    float2 hf = __half22float2(h);
    __half2 l = __float22half2_rn(make_float2(a - hf.x, b - hf.y));
    hi = *(uint32_t*)&h;
    lo = *(uint32_t*)&l;
}

// ============================================================================
// fp32 -> fp16 single conversion (3 inputs, one launch)
// ============================================================================
struct ConvParams {
    const float* x[3];
    __half* y[3];
};

__global__ __launch_bounds__(256)
void conv_half_multi(ConvParams p, int n4_each)
{
    int gi = blockIdx.x * blockDim.x + threadIdx.x;
    const int which = gi / n4_each;
    const int i = gi - which * n4_each;
    float4 v = ((const float4*)p.x[which])[i];
    uint2 o;
    o.x = packh(v.x, v.y);
    o.y = packh(v.z, v.w);
    ((uint2*)p.y[which])[i] = o;
}

// fp32 -> (fp16 hi, fp16 lo) split (4 weights, one launch)
struct SplitHParams {
    const float* x[4];
    __half* hi[4];
    __half* lo[4];
};

__global__ __launch_bounds__(256)
void split_half_multi(SplitHParams p, int n4_each)
{
    int gi = blockIdx.x * blockDim.x + threadIdx.x;
    const int which = gi / n4_each;
    const int i = gi - which * n4_each;
    float4 v = ((const float4*)p.x[which])[i];
    uint2 hh, ll;
    split2h(v.x, v.y, hh.x, ll.x);
    split2h(v.z, v.w, hh.y, ll.y);
    ((uint2*)p.hi[which])[i] = hh;
    ((uint2*)p.lo[which])[i] = ll;
}

// ============================================================================
// Tensor-core GEMM, cp.async 2-stage pipelined, fp16 asymmetric limbs:
//   C[M,N] = A[M,K] * W[N,K]^T + bias[N],  A single fp16, W 2-limb fp16.
// Block tile 128x64, K-chunk 32. 8 warps, warp tile 64x16. 2 mma per atom.
// outMode: 0 fp32; 1 fp16; 2 2-limb.
// ============================================================================
#define TBK 32
#define TROW 40                  // smem row stride (fp16): 80B, conflict-free ldmatrix
#define GA_BYTES (128*TROW*2)    // 10240
#define GB_BYTES (64*TROW*2)     // 5120
#define GSTAGE (GA_BYTES + 2*GB_BYTES)   // 20480
#define GS_TOTAL (2*GSTAGE)              // 40960

struct QKVParams {
    const __half* A[3];
    const __half* Wh[3];
    const __half* Wl[3];
    const float* bias[3];
    __half* C1[3];
    __half* C2h[3];
    __half* C2l[3];
};

__device__ __forceinline__ void gemm_body(
    const __half* __restrict__ A,
    const __half* __restrict__ Bh, const __half* __restrict__ Bl,
    const float* __restrict__ bias, float* __restrict__ C,
    __half* __restrict__ C1, __half* __restrict__ C2h, __half* __restrict__ C2l,
    int N, int K, int outMode, char* dynsm)
{
    const uint32_t uS = smem_u32(dynsm);
    const int t    = threadIdx.x;
    const int wid  = t >> 5;
    const int lane = t & 31;
    const int m0 = blockIdx.y * 128;
    const int n0 = blockIdx.x * 64;
    const int wm = (wid & 1) * 64;
    const int wn = (wid >> 1) * 16;
    const int nchunk = K / TBK;

    const int lrow0 = t >> 2;            // 0..63
    const int lcc   = (t & 3) * 8;       // fp16 col: 0,8,16,24

#define G_ISSUE(c, s) do {                                                     \
        const int _k0 = (c) * TBK;                                             \
        const uint32_t _b = uS + (uint32_t)(s) * GSTAGE;                       \
        const uint32_t _so = (uint32_t)((lrow0 * TROW + lcc) * 2);             \
        cp16(_b + _so, A + (size_t)(m0 + lrow0) * K + _k0 + lcc);              \
        cp16(_b + (uint32_t)(64 * TROW * 2) + _so,                             \
             A + (size_t)(m0 + 64 + lrow0) * K + _k0 + lcc);                   \
        cp16(_b + GA_BYTES + _so,                                              \
             Bh + (size_t)(n0 + lrow0) * K + _k0 + lcc);                       \
        cp16(_b + GA_BYTES + GB_BYTES + _so,                                   \
             Bl + (size_t)(n0 + lrow0) * K + _k0 + lcc);                       \
        CP_COMMIT();                                                           \
    } while (0)

    float acc[4][2][4];
#pragma unroll
    for (int i = 0; i < 4; i++)
#pragma unroll
        for (int j = 0; j < 2; j++)
#pragma unroll
            for (int r = 0; r < 4; r++) acc[i][j][r] = 0.f;

    G_ISSUE(0, 0);

    for (int c = 0; c < nchunk; c++) {
        const int s = c & 1;
        CP_WAIT0();
        __syncthreads();   // orders prev-iter reads of the other stage vs new writes
        if (c + 1 < nchunk) G_ISSUE(c + 1, 1 - s);

        const uint32_t uA  = uS + (uint32_t)(s) * GSTAGE;
        const uint32_t uBh = uA + GA_BYTES;
        const uint32_t uBl = uBh + GB_BYTES;

#pragma unroll
        for (int ks = 0; ks < 2; ks++) {
            uint32_t a[4][4];
#pragma unroll
            for (int ma = 0; ma < 4; ma++) {
                const int row = wm + ma * 16 + (lane & 15);
                const uint32_t off = (uint32_t)(row * TROW * 2 + ks * 32 + (lane >> 4) * 16);
                ldsm_x4(a[ma][0], a[ma][1], a[ma][2], a[ma][3], uA + off);
            }
            uint32_t bh[2][2], bl[2][2];
            {
                const int m = lane >> 3;
                const int row = wn + (m >> 1) * 8 + (lane & 7);
                const uint32_t off = (uint32_t)(row * TROW * 2 + ks * 32 + (m & 1) * 16);
                ldsm_x4(bh[0][0], bh[0][1], bh[1][0], bh[1][1], uBh + off);
                ldsm_x4(bl[0][0], bl[0][1], bl[1][0], bl[1][1], uBl + off);
            }
#pragma unroll
            for (int ma = 0; ma < 4; ma++)
#pragma unroll
                for (int na = 0; na < 2; na++) {
                    float* cc = acc[ma][na];
                    mma_f16(cc[0], cc[1], cc[2], cc[3],
                            a[ma][0], a[ma][1], a[ma][2], a[ma][3],
                            bh[na][0], bh[na][1]);
                    mma_f16(cc[0], cc[1], cc[2], cc[3],
                            a[ma][0], a[ma][1], a[ma][2], a[ma][3],
                            bl[na][0], bl[na][1]);
                }
        }
    }

    const int g = lane >> 2;
    const int q = lane & 3;
#pragma unroll
    for (int ma = 0; ma < 4; ma++) {
#pragma unroll
        for (int na = 0; na < 2; na++) {
            const int col = n0 + wn + na * 8 + q * 2;
            const float b0 = bias[col], b1 = bias[col + 1];
            const int r0 = m0 + wm + ma * 16 + g;
            const float v00 = acc[ma][na][0] + b0, v01 = acc[ma][na][1] + b1;
            const float v10 = acc[ma][na][2] + b0, v11 = acc[ma][na][3] + b1;
            if (outMode == 1) {
                *(uint32_t*)(C1 + (size_t)r0 * N + col)       = packh(v00, v01);
                *(uint32_t*)(C1 + (size_t)(r0 + 8) * N + col) = packh(v10, v11);
            } else if (outMode == 2) {
                uint32_t h, l;
                split2h(v00, v01, h, l);
                *(uint32_t*)(C2h + (size_t)r0 * N + col) = h;
                *(uint32_t*)(C2l + (size_t)r0 * N + col) = l;
                split2h(v10, v11, h, l);
                *(uint32_t*)(C2h + (size_t)(r0 + 8) * N + col) = h;
                *(uint32_t*)(C2l + (size_t)(r0 + 8) * N + col) = l;
            } else {
                float* d0 = C + (size_t)r0 * N + col;
                d0[0] = v00; d0[1] = v01;
                float* d1 = C + (size_t)(r0 + 8) * N + col;
                d1[0] = v10; d1[1] = v11;
            }
        }
    }
#undef G_ISSUE
}

__global__ __launch_bounds__(256)
void gemm_qkv(QKVParams p)
{
    extern __shared__ char dynsm[];
    const int z = blockIdx.z;
    gemm_body(p.A[z], p.Wh[z], p.Wl[z], p.bias[z],
              nullptr, p.C1[z], p.C2h[z], p.C2l[z], DD, DD,
              (z == 0) ? 1 : 2, dynsm);
}

__global__ __launch_bounds__(256)
void gemm_o(const __half* __restrict__ A,
            const __half* __restrict__ Bh, const __half* __restrict__ Bl,
            const float* __restrict__ bias, float* __restrict__ C)
{
    extern __shared__ char dynsm[];
    gemm_body(A, Bh, Bl, bias, C, nullptr, nullptr, nullptr, DD, DD, 0, dynsm);
}

// ============================================================================
// Flash attention on mma.sync fp16, cp.async double-buffered K/V.
// HIGH-OCCUPANCY VARIANT: 128 threads (4 warps), q-tile 64, 32-key K/V tiles.
// smem ~46.6KB -> 4 CTAs/SM (32 warps/SM). Per-warp tile 16 rows x 32 keys.
// GEMM1: Q single fp16 x K 2-limb. GEMM2: P fp16 x V 2-limb.
// ============================================================================
#define FST 72                        // smem row stride (fp16): 144 B
#define FSTB (FST*2)
#define FBQ 64                        // q-rows per CTA
#define FBK 32                        // keys per tile
#define QTILEB (FBQ*FSTB)             // 9216 B
#define KTILEB (FBK*FSTB)             // 4608 B per array per stage
#define FKV QTILEB
#define FMS (FKV + 8*KTILEB)          // int ms[2][32]
#define FLASH_SMEM_BYTES (FMS + 256)  // 46336 B

__global__ __launch_bounds__(128, 4)
void flash_tc(const __half* __restrict__ Q1,
              const __half* __restrict__ Kh, const __half* __restrict__ Kl,
              const __half* __restrict__ Vh, const __half* __restrict__ Vl,
              const int* __restrict__ mask,
              __half* __restrict__ C1)
{
    extern __shared__ char dynsm[];
    const uint32_t uS = smem_u32(dynsm);
    const uint32_t uQ = uS;
    int* ms = (int*)(dynsm + FMS);

    const int t    = threadIdx.x;
    const int wid  = t >> 5;          // 0..3
    const int lane = t & 31;
    const int g    = lane >> 2;
    const int q    = lane & 3;
    const int i0   = blockIdx.x * FBQ;
    const int h    = blockIdx.y;
    const int b    = blockIdx.z;
    const size_t base = (size_t)b * SS * DD + (size_t)h * DK;

    // Load Q tile (plain stores; first loop-top sync publishes them)
    {
        __half* sQ = (__half*)dynsm;
#pragma unroll
        for (int p = 0; p < 4; p++) {
            const int idx = t + p * 128;
            const int row = idx >> 3;
            const int c   = (idx & 7) * 8;
            *(uint4*)(sQ + row * FST + c) =
                *(const uint4*)(Q1 + base + (size_t)(i0 + row) * DD + c);
        }
    }

    const int lrow = t >> 3;         // 0..15
    const int lcc  = (t & 7) * 8;    // fp16 col

#define F_ISSUE(jt, s) do {                                                    \
        const int _j0 = (jt) * FBK;                                            \
        _Pragma("unroll")                                                      \
        for (int _p = 0; _p < 2; _p++) {                                       \
            const int _row = lrow + _p * 16;                                   \
            const size_t _gk = base + (size_t)(_j0 + _row) * DD + lcc;         \
            const uint32_t _so = (uint32_t)(_row * FSTB + lcc * 2);            \
            cp16(uS + FKV + (uint32_t)(0 * 2 + (s)) * KTILEB + _so, Kh + _gk); \
            cp16(uS + FKV + (uint32_t)(1 * 2 + (s)) * KTILEB + _so, Kl + _gk); \
            cp16(uS + FKV + (uint32_t)(2 * 2 + (s)) * KTILEB + _so, Vh + _gk); \
            cp16(uS + FKV + (uint32_t)(3 * 2 + (s)) * KTILEB + _so, Vl + _gk); \
        }                                                                      \
        if (t < 8)                                                             \
            asm volatile("cp.async.ca.shared.global [%0], [%1], 16;"           \
                :: "r"(uS + FMS + (uint32_t)(s) * 128 + (uint32_t)t * 16),     \
                   "l"(mask + (size_t)b * SS + _j0 + t * 4));                  \
        CP_COMMIT();                                                           \
    } while (0)

    float o[8][4];
#pragma unroll
    for (int na = 0; na < 8; na++)
#pragma unroll
        for (int r = 0; r < 4; r++) o[na][r] = 0.f;
    float m0 = -INFINITY, m1 = -INFINITY, l0 = 0.f, l1 = 0.f;
    const float scale2 = 0.125f * 1.44269504089f;  // 1/sqrt(64) * log2(e)

    F_ISSUE(0, 0);

    for (int jt = 0; jt < SS / FBK; jt++) {
        const int s = jt & 1;
        CP_WAIT0();
        __syncthreads();
        if (jt + 1 < SS / FBK) F_ISSUE(jt + 1, 1 - s);

        const uint32_t uKh = uS + FKV + (uint32_t)(0 * 2 + s) * KTILEB;
        const uint32_t uKl = uS + FKV + (uint32_t)(1 * 2 + s) * KTILEB;
        const uint32_t uVh = uS + FKV + (uint32_t)(2 * 2 + s) * KTILEB;
        const uint32_t uVl = uS + FKV + (uint32_t)(3 * 2 + s) * KTILEB;
        const int* msj = ms + s * 32;

        // ---- GEMM1: S[16 rows x 32 keys] per warp (Q single, K 2-limb) ----
        float sc[4][4];
#pragma unroll
        for (int na = 0; na < 4; na++)
#pragma unroll
            for (int r = 0; r < 4; r++) sc[na][r] = 0.f;

#pragma unroll
        for (int ks = 0; ks < 4; ks++) {
            uint32_t a[4];
            const uint32_t aoff = (uint32_t)((wid * 16 + (lane & 15)) * FSTB
                                             + ks * 32 + (lane >> 4) * 16);
            ldsm_x4(a[0], a[1], a[2], a[3], uQ + aoff);
#pragma unroll
            for (int np = 0; np < 2; np++) {
                const int m = lane >> 3;
                const int row = np * 16 + (m >> 1) * 8 + (lane & 7);
                const uint32_t boff = (uint32_t)(row * FSTB + ks * 32 + (m & 1) * 16);
                uint32_t b0h, b1h, b2h, b3h, b0l, b1l, b2l, b3l;
                ldsm_x4(b0h, b1h, b2h, b3h, uKh + boff);
                ldsm_x4(b0l, b1l, b2l, b3l, uKl + boff);
                const int na0 = np * 2, na1 = np * 2 + 1;
                mma_f16(sc[na0][0], sc[na0][1], sc[na0][2], sc[na0][3],
                        a[0], a[1], a[2], a[3], b0h, b1h);
                mma_f16(sc[na0][0], sc[na0][1], sc[na0][2], sc[na0][3],
                        a[0], a[1], a[2], a[3], b0l, b1l);
                mma_f16(sc[na1][0], sc[na1][1], sc[na1][2], sc[na1][3],
                        a[0], a[1], a[2], a[3], b2h, b3h);
                mma_f16(sc[na1][0], sc[na1][1], sc[na1][2], sc[na1][3],
                        a[0], a[1], a[2], a[3], b2l, b3l);
            }
        }

        // ---- scale (exp2 domain) + mask ----
#pragma unroll
        for (int na = 0; na < 4; na++) {
            const int kc = na * 8 + q * 2;
            const int mk0 = msj[kc], mk1 = msj[kc + 1];
            sc[na][0] = mk0 ? sc[na][0] * scale2 : -1e9f;
            sc[na][1] = mk1 ? sc[na][1] * scale2 : -1e9f;
            sc[na][2] = mk0 ? sc[na][2] * scale2 : -1e9f;
            sc[na][3] = mk1 ? sc[na][3] * scale2 : -1e9f;
        }

        // ---- online softmax (rows g, g+8; 4 lanes per row) ----
        float mx0 = -INFINITY, mx1 = -INFINITY;
#pragma unroll
        for (int na = 0; na < 4; na++) {
            mx0 = fmaxf(mx0, fmaxf(sc[na][0], sc[na][1]));
            mx1 = fmaxf(mx1, fmaxf(sc[na][2], sc[na][3]));
        }
        mx0 = fmaxf(mx0, __shfl_xor_sync(0xffffffffu, mx0, 1));
        mx0 = fmaxf(mx0, __shfl_xor_sync(0xffffffffu, mx0, 2));
        mx1 = fmaxf(mx1, __shfl_xor_sync(0xffffffffu, mx1, 1));
        mx1 = fmaxf(mx1, __shfl_xor_sync(0xffffffffu, mx1, 2));
        const float mn0 = fmaxf(m0, mx0), mn1 = fmaxf(m1, mx1);
        const float a0 = ex2(m0 - mn0), a1 = ex2(m1 - mn1);

        // P = exp2(sc - mn) in f16x2, fragments mma-ready
        uint32_t pA[4], pB[4];
        float sum0 = 0.f, sum1 = 0.f;
#pragma unroll
        for (int na = 0; na < 4; na++) {
            pA[na] = h2ex2(packh(sc[na][0] - mn0, sc[na][1] - mn0));
            pB[na] = h2ex2(packh(sc[na][2] - mn1, sc[na][3] - mn1));
            float2 f0 = __half22float2(*(__half2*)&pA[na]);
            float2 f1 = __half22float2(*(__half2*)&pB[na]);
            sum0 += f0.x + f0.y;
            sum1 += f1.x + f1.y;
        }
        sum0 += __shfl_xor_sync(0xffffffffu, sum0, 1);
        sum0 += __shfl_xor_sync(0xffffffffu, sum0, 2);
        sum1 += __shfl_xor_sync(0xffffffffu, sum1, 1);
        sum1 += __shfl_xor_sync(0xffffffffu, sum1, 2);
        l0 = l0 * a0 + sum0;
        l1 = l1 * a1 + sum1;
        m0 = mn0; m1 = mn1;
#pragma unroll
        for (int na = 0; na < 8; na++) {
            o[na][0] *= a0; o[na][1] *= a0;
            o[na][2] *= a1; o[na][3] *= a1;
        }

        // ---- GEMM2: O += P(fp16) * V(fp16 2-limb), V via ldmatrix.x4.trans ----
#pragma unroll
        for (int kk = 0; kk < 2; kk++) {
            const uint32_t ph0 = pA[2*kk],   ph1 = pB[2*kk];
            const uint32_t ph2 = pA[2*kk+1], ph3 = pB[2*kk+1];
            const int m = lane >> 3;
#pragma unroll
            for (int np = 0; np < 4; np++) {
                const int row = kk * 16 + (m & 1) * 8 + (lane & 7);
                const int na0 = np * 2, na1 = np * 2 + 1;
                const uint32_t voff = (uint32_t)(row * FSTB + (np * 2 + (m >> 1)) * 16);
                uint32_t v0h, v1h, v2h, v3h, v0l, v1l, v2l, v3l;
                ldsm_x4t(v0h, v1h, v2h, v3h, uVh + voff);
                ldsm_x4t(v0l, v1l, v2l, v3l, uVl + voff);
                mma_f16(o[na0][0], o[na0][1], o[na0][2], o[na0][3],
                        ph0, ph1, ph2, ph3, v0h, v1h);
                mma_f16(o[na0][0], o[na0][1], o[na0][2], o[na0][3],
                        ph0, ph1, ph2, ph3, v0l, v1l);
                mma_f16(o[na1][0], o[na1][1], o[na1][2], o[na1][3],
                        ph0, ph1, ph2, ph3, v2h, v3h);
                mma_f16(o[na1][0], o[na1][1], o[na1][2], o[na1][3],
                        ph0, ph1, ph2, ph3, v2l, v3l);
            }
        }
    }

    // ---- epilogue: divide by l, write context as single fp16 ----
    const float inv0 = 1.f / l0, inv1 = 1.f / l1;
    const int r0 = i0 + wid * 16 + g;
#pragma unroll
    for (int na = 0; na < 8; na++) {
        const int col = na * 8 + q * 2;
        *(uint32_t*)(C1 + base + (size_t)r0 * DD + col) =
            packh(o[na][0] * inv0, o[na][1] * inv0);
        *(uint32_t*)(C1 + base + (size_t)(r0 + 8) * DD + col) =
            packh(o[na][2] * inv1, o[na][3] * inv1);
    }
}

// ============================================================================
// kernel_launch
// ============================================================================
extern "C" void kernel_launch(void* const* d_in, const int* in_sizes, int n_in,
                              void* d_out, int out_size)
{
    const float* q    = (const float*)d_in[0];
    const float* k    = (const float*)d_in[1];
    const float* v    = (const float*)d_in[2];
    const int*   mask = (const int*)  d_in[3];
    const float* wq   = (const float*)d_in[4];
    const float* bq   = (const float*)d_in[5];
    const float* wk   = (const float*)d_in[6];
    const float* bk   = (const float*)d_in[7];
    const float* wv   = (const float*)d_in[8];
    const float* bv   = (const float*)d_in[9];
    const float* wo   = (const float*)d_in[10];
    const float* bo   = (const float*)d_in[11];
    float* out = (float*)d_out;

    __half *aq, *ak, *av;
    __half *wqh, *wql, *wkh, *wkl, *wvh, *wvl, *woh, *wol;
    __half *q1, *kh, *kl, *vh, *vl, *c1;
    cudaGetSymbolAddress((void**)&aq,  g_Aq);
    cudaGetSymbolAddress((void**)&ak,  g_Ak);
    cudaGetSymbolAddress((void**)&av,  g_Av);
    cudaGetSymbolAddress((void**)&wqh, g_WQh);
    cudaGetSymbolAddress((void**)&wql, g_WQl);
    cudaGetSymbolAddress((void**)&wkh, g_WKh);
    cudaGetSymbolAddress((void**)&wkl, g_WKl);
    cudaGetSymbolAddress((void**)&wvh, g_WVh);
    cudaGetSymbolAddress((void**)&wvl, g_WVl);
    cudaGetSymbolAddress((void**)&woh, g_WOh);
    cudaGetSymbolAddress((void**)&wol, g_WOl);
    cudaGetSymbolAddress((void**)&q1,  g_Q1);
    cudaGetSymbolAddress((void**)&kh,  g_Kh);
    cudaGetSymbolAddress((void**)&kl,  g_Kl);
    cudaGetSymbolAddress((void**)&vh,  g_Vh);
    cudaGetSymbolAddress((void**)&vl,  g_Vl);
    cudaGetSymbolAddress((void**)&c1,  g_C1);

    static bool attr_set = false;
    if (!attr_set) {
        cudaFuncSetAttribute(flash_tc, cudaFuncAttributeMaxDynamicSharedMemorySize,
                             FLASH_SMEM_BYTES);
        cudaFuncSetAttribute(gemm_qkv, cudaFuncAttributeMaxDynamicSharedMemorySize,
                             GS_TOTAL);
        cudaFuncSetAttribute(gemm_o, cudaFuncAttributeMaxDynamicSharedMemorySize,
                             GS_TOTAL);
        attr_set = true;
    }

    const int nA4 = NROWS * DD / 4;   // 1,048,576
    const int nW4 = DD * DD / 4;      //   262,144

    // Input conversions (fp16 single) and weight splits (fp16 2-limb)
    {
        ConvParams cp{};
        cp.x[0] = q; cp.y[0] = aq;
        cp.x[1] = k; cp.y[1] = ak;
        cp.x[2] = v; cp.y[2] = av;
        conv_half_multi<<<3 * nA4 / 256, 256>>>(cp, nA4);
    }
    {
        SplitHParams sp{};
        sp.x[0] = wq; sp.hi[0] = wqh; sp.lo[0] = wql;
        sp.x[1] = wk; sp.hi[1] = wkh; sp.lo[1] = wkl;
        sp.x[2] = wv; sp.hi[2] = wvh; sp.lo[2] = wvl;
        sp.x[3] = wo; sp.hi[3] = woh; sp.lo[3] = wol;
        split_half_multi<<<4 * nW4 / 256, 256>>>(sp, nW4);
    }

    // Batched Q/K/V projections: z=0 Q (single out), z=1 K, z=2 V (2-limb out)
    {
        QKVParams p{};
        p.A[0] = aq; p.Wh[0] = wqh; p.Wl[0] = wql; p.bias[0] = bq;
        p.C1[0] = q1; p.C2h[0] = nullptr; p.C2l[0] = nullptr;
        p.A[1] = ak; p.Wh[1] = wkh; p.Wl[1] = wkl; p.bias[1] = bk;
        p.C1[1] = nullptr; p.C2h[1] = kh; p.C2l[1] = kl;
        p.A[2] = av; p.Wh[2] = wvh; p.Wl[2] = wvl; p.bias[2] = bv;
        p.C1[2] = nullptr; p.C2h[2] = vh; p.C2l[2] = vl;
        dim3 tgrid(DD / 64, NROWS / 128, 3);   // (16, 32, 3) = 1536 CTAs
        gemm_qkv<<<tgrid, 256, GS_TOTAL>>>(p);
    }

    // Attention (high-occupancy: 128 threads, 64 q-rows per CTA)
    dim3 fgrid(SS / FBQ, HH, BB);        // (32, 16, 2) = 1024 CTAs
    flash_tc<<<fgrid, 128, FLASH_SMEM_BYTES>>>(q1, kh, kl, vh, vl, mask, c1);

    // Output projection (fp32 out)
    dim3 ogrid(DD / 64, NROWS / 128);    // (16, 32) = 512 CTAs
    gemm_o<<<ogrid, 256, GS_TOTAL>>>(c1, woh, wol, bo, out);
}

// round 17
// speedup vs baseline: 1.5717x; 1.0851x over previous
#include <cuda_runtime.h>
#include <cuda_bf16.h>
#include <cuda_fp16.h>
#include <math.h>
#include <stdint.h>

// Problem constants
#define BB   2
#define SS   2048
#define DD   1024
#define HH   16
#define DK   64
#define NROWS (BB*SS)   // 4096

// Scratch (allocation-free rule: device globals) — fp16 scheme:
// A-operands single fp16; K/W B-operands 2-limb fp16; V single fp16.
__device__ __half g_Aq[NROWS*DD];
__device__ __half g_Ak[NROWS*DD];
__device__ __half g_Av[NROWS*DD];
__device__ __half g_WQh[DD*DD];
__device__ __half g_WQl[DD*DD];
__device__ __half g_WKh[DD*DD];
__device__ __half g_WKl[DD*DD];
__device__ __half g_WVh[DD*DD];
__device__ __half g_WVl[DD*DD];
__device__ __half g_WOh[DD*DD];
__device__ __half g_WOl[DD*DD];
__device__ __half g_Q1[NROWS*DD];    // Q projection, single fp16 (A of GEMM1)
__device__ __half g_Kh[NROWS*DD];    // K projection, 2-limb (B of GEMM1)
__device__ __half g_Kl[NROWS*DD];
__device__ __half g_V1[NROWS*DD];    // V projection, single fp16 (B of GEMM2)
__device__ __half g_C1[NROWS*DD];    // context, single fp16 (A of O-proj)

// ---------------------------------------------------------------------------
// Base-ISA helpers: ldmatrix + mma.sync + cp.async (all compile for sm_103)
// ---------------------------------------------------------------------------
__device__ __forceinline__ uint32_t smem_u32(const void* p) {
    uint32_t a;
    asm("{ .reg .u64 t; cvta.to.shared.u64 t, %1; cvt.u32.u64 %0, t; }" : "=r"(a) : "l"(p));
    return a;
}
__device__ __forceinline__ void ldsm_x4(uint32_t& r0, uint32_t& r1, uint32_t& r2,
                                        uint32_t& r3, uint32_t addr) {
    asm volatile("ldmatrix.sync.aligned.m8n8.x4.shared.b16 {%0,%1,%2,%3}, [%4];"
                 : "=r"(r0), "=r"(r1), "=r"(r2), "=r"(r3) : "r"(addr));
}
__device__ __forceinline__ void ldsm_x4t(uint32_t& r0, uint32_t& r1, uint32_t& r2,
                                         uint32_t& r3, uint32_t addr) {
    asm volatile("ldmatrix.sync.aligned.m8n8.x4.trans.shared.b16 {%0,%1,%2,%3}, [%4];"
                 : "=r"(r0), "=r"(r1), "=r"(r2), "=r"(r3) : "r"(addr));
}
__device__ __forceinline__ void mma_f16(float& c0, float& c1, float& c2, float& c3,
                                        uint32_t a0, uint32_t a1, uint32_t a2, uint32_t a3,
                                        uint32_t b0, uint32_t b1) {
    asm volatile("mma.sync.aligned.m16n8k16.row.col.f32.f16.f16.f32 "
                 "{%0,%1,%2,%3}, {%4,%5,%6,%7}, {%8,%9}, {%0,%1,%2,%3};"
                 : "+f"(c0), "+f"(c1), "+f"(c2), "+f"(c3)
                 : "r"(a0), "r"(a1), "r"(a2), "r"(a3), "r"(b0), "r"(b1));
}
__device__ __forceinline__ void cp16(uint32_t saddr, const void* g) {
    asm volatile("cp.async.cg.shared.global [%0], [%1], 16;" :: "r"(saddr), "l"(g));
}
#define CP_COMMIT() asm volatile("cp.async.commit_group;" ::: "memory")
#define CP_WAIT0()  asm volatile("cp.async.wait_group 0;"  ::: "memory")

__device__ __forceinline__ float ex2(float x) {
    float r; asm("ex2.approx.f32 %0, %1;" : "=f"(r) : "f"(x)); return r;
}
// f16x2 exp2: two fp16 exponentials in one MUFU op
__device__ __forceinline__ uint32_t h2ex2(uint32_t x) {
    uint32_t r; asm("ex2.approx.f16x2 %0, %1;" : "=r"(r) : "r"(x)); return r;
}
// pack two fp32 into f16x2 (lo half = first arg)
__device__ __forceinline__ uint32_t packh(float lo, float hi) {
    uint32_t r;
    asm("cvt.rn.f16x2.f32 %0, %1, %2;" : "=r"(r) : "f"(hi), "f"(lo));
    return r;
}
// split a pair of fp32 into f16x2 hi and f16x2 lo (packed uint32)
__device__ __forceinline__ void split2h(float a, float b, uint32_t& hi, uint32_t& lo) {
    __half2 h = __float22half2_rn(make_float2(a, b));
    float2 hf = __half22float2(h);
    __half2 l = __float22half2_rn(make_float2(a - hf.x, b - hf.y));
    hi = *(uint32_t*)&h;
    lo = *(uint32_t*)&l;
}

// ============================================================================
// fp32 -> fp16 single conversion (3 inputs, one launch)
// ============================================================================
struct ConvParams {
    const float* x[3];
    __half* y[3];
};

__global__ __launch_bounds__(256)
void conv_half_multi(ConvParams p, int n4_each)
{
    int gi = blockIdx.x * blockDim.x + threadIdx.x;
    const int which = gi / n4_each;
    const int i = gi - which * n4_each;
    float4 v = ((const float4*)p.x[which])[i];
    uint2 o;
    o.x = packh(v.x, v.y);
    o.y = packh(v.z, v.w);
    ((uint2*)p.y[which])[i] = o;
}

// fp32 -> (fp16 hi, fp16 lo) split (4 weights, one launch)
struct SplitHParams {
    const float* x[4];
    __half* hi[4];
    __half* lo[4];
};

__global__ __launch_bounds__(256)
void split_half_multi(SplitHParams p, int n4_each)
{
    int gi = blockIdx.x * blockDim.x + threadIdx.x;
    const int which = gi / n4_each;
    const int i = gi - which * n4_each;
    float4 v = ((const float4*)p.x[which])[i];
    uint2 hh, ll;
    split2h(v.x, v.y, hh.x, ll.x);
    split2h(v.z, v.w, hh.y, ll.y);
    ((uint2*)p.hi[which])[i] = hh;
    ((uint2*)p.lo[which])[i] = ll;
}

// ============================================================================
// Tensor-core GEMM, cp.async 2-stage pipelined, fp16 asymmetric limbs:
//   C[M,N] = A[M,K] * W[N,K]^T + bias[N],  A single fp16, W 2-limb fp16.
// Block tile 128x64, K-chunk 32. 8 warps, warp tile 64x16. 2 mma per atom.
// outMode: 0 fp32; 1 fp16; 2 2-limb.
// ============================================================================
#define TBK 32
#define TROW 40                  // smem row stride (fp16): 80B, conflict-free ldmatrix
#define GA_BYTES (128*TROW*2)    // 10240
#define GB_BYTES (64*TROW*2)     // 5120
#define GSTAGE (GA_BYTES + 2*GB_BYTES)   // 20480
#define GS_TOTAL (2*GSTAGE)              // 40960

struct QKVParams {
    const __half* A[3];
    const __half* Wh[3];
    const __half* Wl[3];
    const float* bias[3];
    __half* C1[3];
    __half* C2h[3];
    __half* C2l[3];
};

__device__ __forceinline__ void gemm_body(
    const __half* __restrict__ A,
    const __half* __restrict__ Bh, const __half* __restrict__ Bl,
    const float* __restrict__ bias, float* __restrict__ C,
    __half* __restrict__ C1, __half* __restrict__ C2h, __half* __restrict__ C2l,
    int N, int K, int outMode, char* dynsm)
{
    const uint32_t uS = smem_u32(dynsm);
    const int t    = threadIdx.x;
    const int wid  = t >> 5;
    const int lane = t & 31;
    const int m0 = blockIdx.y * 128;
    const int n0 = blockIdx.x * 64;
    const int wm = (wid & 1) * 64;
    const int wn = (wid >> 1) * 16;
    const int nchunk = K / TBK;

    const int lrow0 = t >> 2;            // 0..63
    const int lcc   = (t & 3) * 8;       // fp16 col: 0,8,16,24

#define G_ISSUE(c, s) do {                                                     \
        const int _k0 = (c) * TBK;                                             \
        const uint32_t _b = uS + (uint32_t)(s) * GSTAGE;                       \
        const uint32_t _so = (uint32_t)((lrow0 * TROW + lcc) * 2);             \
        cp16(_b + _so, A + (size_t)(m0 + lrow0) * K + _k0 + lcc);              \
        cp16(_b + (uint32_t)(64 * TROW * 2) + _so,                             \
             A + (size_t)(m0 + 64 + lrow0) * K + _k0 + lcc);                   \
        cp16(_b + GA_BYTES + _so,                                              \
             Bh + (size_t)(n0 + lrow0) * K + _k0 + lcc);                       \
        cp16(_b + GA_BYTES + GB_BYTES + _so,                                   \
             Bl + (size_t)(n0 + lrow0) * K + _k0 + lcc);                       \
        CP_COMMIT();                                                           \
    } while (0)

    float acc[4][2][4];
#pragma unroll
    for (int i = 0; i < 4; i++)
#pragma unroll
        for (int j = 0; j < 2; j++)
#pragma unroll
            for (int r = 0; r < 4; r++) acc[i][j][r] = 0.f;

    G_ISSUE(0, 0);

    for (int c = 0; c < nchunk; c++) {
        const int s = c & 1;
        CP_WAIT0();
        __syncthreads();   // orders prev-iter reads of the other stage vs new writes
        if (c + 1 < nchunk) G_ISSUE(c + 1, 1 - s);

        const uint32_t uA  = uS + (uint32_t)(s) * GSTAGE;
        const uint32_t uBh = uA + GA_BYTES;
        const uint32_t uBl = uBh + GB_BYTES;

#pragma unroll
        for (int ks = 0; ks < 2; ks++) {
            uint32_t a[4][4];
#pragma unroll
            for (int ma = 0; ma < 4; ma++) {
                const int row = wm + ma * 16 + (lane & 15);
                const uint32_t off = (uint32_t)(row * TROW * 2 + ks * 32 + (lane >> 4) * 16);
                ldsm_x4(a[ma][0], a[ma][1], a[ma][2], a[ma][3], uA + off);
            }
            uint32_t bh[2][2], bl[2][2];
            {
                const int m = lane >> 3;
                const int row = wn + (m >> 1) * 8 + (lane & 7);
                const uint32_t off = (uint32_t)(row * TROW * 2 + ks * 32 + (m & 1) * 16);
                ldsm_x4(bh[0][0], bh[0][1], bh[1][0], bh[1][1], uBh + off);
                ldsm_x4(bl[0][0], bl[0][1], bl[1][0], bl[1][1], uBl + off);
            }
#pragma unroll
            for (int ma = 0; ma < 4; ma++)
#pragma unroll
                for (int na = 0; na < 2; na++) {
                    float* cc = acc[ma][na];
                    mma_f16(cc[0], cc[1], cc[2], cc[3],
                            a[ma][0], a[ma][1], a[ma][2], a[ma][3],
                            bh[na][0], bh[na][1]);
                    mma_f16(cc[0], cc[1], cc[2], cc[3],
                            a[ma][0], a[ma][1], a[ma][2], a[ma][3],
                            bl[na][0], bl[na][1]);
                }
        }
    }

    const int g = lane >> 2;
    const int q = lane & 3;
#pragma unroll
    for (int ma = 0; ma < 4; ma++) {
#pragma unroll
        for (int na = 0; na < 2; na++) {
            const int col = n0 + wn + na * 8 + q * 2;
            const float b0 = bias[col], b1 = bias[col + 1];
            const int r0 = m0 + wm + ma * 16 + g;
            const float v00 = acc[ma][na][0] + b0, v01 = acc[ma][na][1] + b1;
            const float v10 = acc[ma][na][2] + b0, v11 = acc[ma][na][3] + b1;
            if (outMode == 1) {
                *(uint32_t*)(C1 + (size_t)r0 * N + col)       = packh(v00, v01);
                *(uint32_t*)(C1 + (size_t)(r0 + 8) * N + col) = packh(v10, v11);
            } else if (outMode == 2) {
                uint32_t h, l;
                split2h(v00, v01, h, l);
                *(uint32_t*)(C2h + (size_t)r0 * N + col) = h;
                *(uint32_t*)(C2l + (size_t)r0 * N + col) = l;
                split2h(v10, v11, h, l);
                *(uint32_t*)(C2h + (size_t)(r0 + 8) * N + col) = h;
                *(uint32_t*)(C2l + (size_t)(r0 + 8) * N + col) = l;
            } else {
                float* d0 = C + (size_t)r0 * N + col;
                d0[0] = v00; d0[1] = v01;
                float* d1 = C + (size_t)(r0 + 8) * N + col;
                d1[0] = v10; d1[1] = v11;
            }
        }
    }
#undef G_ISSUE
}

__global__ __launch_bounds__(256)
void gemm_qkv(QKVParams p)
{
    extern __shared__ char dynsm[];
    const int z = blockIdx.z;
    // z=0: Q -> single fp16; z=1: K -> 2-limb; z=2: V -> single fp16
    gemm_body(p.A[z], p.Wh[z], p.Wl[z], p.bias[z],
              nullptr, p.C1[z], p.C2h[z], p.C2l[z], DD, DD,
              (z == 1) ? 2 : 1, dynsm);
}

__global__ __launch_bounds__(256)
void gemm_o(const __half* __restrict__ A,
            const __half* __restrict__ Bh, const __half* __restrict__ Bl,
            const float* __restrict__ bias, float* __restrict__ C)
{
    extern __shared__ char dynsm[];
    gemm_body(A, Bh, Bl, bias, C, nullptr, nullptr, nullptr, DD, DD, 0, dynsm);
}

// ============================================================================
// Flash attention on mma.sync fp16, cp.async double-buffered K/V.
// 128 threads (4 warps), q-tile 64, 32-key tiles. V SINGLE fp16.
// smem ~37.1KB, regs <=102 -> 5 CTAs/SM (20 warps).
// GEMM1: Q single fp16 x K 2-limb. GEMM2: P fp16 x V single.
// ============================================================================
#define FST 72                        // smem row stride (fp16): 144 B
#define FSTB (FST*2)
#define FBQ 64                        // q-rows per CTA
#define FBK 32                        // keys per tile
#define QTILEB (FBQ*FSTB)             // 9216 B
#define KTILEB (FBK*FSTB)             // 4608 B per array per stage
#define FKV QTILEB
#define FMS (FKV + 6*KTILEB)          // 3 arrays (Kh,Kl,V) x 2 stages
#define FLASH_SMEM_BYTES (FMS + 256)  // 37120 B

__global__ __launch_bounds__(128, 5)
void flash_tc(const __half* __restrict__ Q1,
              const __half* __restrict__ Kh, const __half* __restrict__ Kl,
              const __half* __restrict__ V1,
              const int* __restrict__ mask,
              __half* __restrict__ C1)
{
    extern __shared__ char dynsm[];
    const uint32_t uS = smem_u32(dynsm);
    const uint32_t uQ = uS;
    int* ms = (int*)(dynsm + FMS);

    const int t    = threadIdx.x;
    const int wid  = t >> 5;          // 0..3
    const int lane = t & 31;
    const int g    = lane >> 2;
    const int q    = lane & 3;
    const int i0   = blockIdx.x * FBQ;
    const int h    = blockIdx.y;
    const int b    = blockIdx.z;
    const size_t base = (size_t)b * SS * DD + (size_t)h * DK;

    // Load Q tile (plain stores; first loop-top sync publishes them)
    {
        __half* sQ = (__half*)dynsm;
#pragma unroll
        for (int p = 0; p < 4; p++) {
            const int idx = t + p * 128;
            const int row = idx >> 3;
            const int c   = (idx & 7) * 8;
            *(uint4*)(sQ + row * FST + c) =
                *(const uint4*)(Q1 + base + (size_t)(i0 + row) * DD + c);
        }
    }

    const int lrow = t >> 3;         // 0..15
    const int lcc  = (t & 7) * 8;    // fp16 col

#define F_ISSUE(jt, s) do {                                                    \
        const int _j0 = (jt) * FBK;                                            \
        _Pragma("unroll")                                                      \
        for (int _p = 0; _p < 2; _p++) {                                       \
            const int _row = lrow + _p * 16;                                   \
            const size_t _gk = base + (size_t)(_j0 + _row) * DD + lcc;         \
            const uint32_t _so = (uint32_t)(_row * FSTB + lcc * 2);            \
            cp16(uS + FKV + (uint32_t)(0 * 2 + (s)) * KTILEB + _so, Kh + _gk); \
            cp16(uS + FKV + (uint32_t)(1 * 2 + (s)) * KTILEB + _so, Kl + _gk); \
            cp16(uS + FKV + (uint32_t)(2 * 2 + (s)) * KTILEB + _so, V1 + _gk); \
        }                                                                      \
        if (t < 8)                                                             \
            asm volatile("cp.async.ca.shared.global [%0], [%1], 16;"           \
                :: "r"(uS + FMS + (uint32_t)(s) * 128 + (uint32_t)t * 16),     \
                   "l"(mask + (size_t)b * SS + _j0 + t * 4));                  \
        CP_COMMIT();                                                           \
    } while (0)

    float o[8][4];
#pragma unroll
    for (int na = 0; na < 8; na++)
#pragma unroll
        for (int r = 0; r < 4; r++) o[na][r] = 0.f;
    float m0 = -INFINITY, m1 = -INFINITY, l0 = 0.f, l1 = 0.f;
    const float scale2 = 0.125f * 1.44269504089f;  // 1/sqrt(64) * log2(e)

    F_ISSUE(0, 0);

    for (int jt = 0; jt < SS / FBK; jt++) {
        const int s = jt & 1;
        CP_WAIT0();
        __syncthreads();
        if (jt + 1 < SS / FBK) F_ISSUE(jt + 1, 1 - s);

        const uint32_t uKh = uS + FKV + (uint32_t)(0 * 2 + s) * KTILEB;
        const uint32_t uKl = uS + FKV + (uint32_t)(1 * 2 + s) * KTILEB;
        const uint32_t uV  = uS + FKV + (uint32_t)(2 * 2 + s) * KTILEB;
        const int* msj = ms + s * 32;

        // ---- GEMM1: S[16 rows x 32 keys] per warp (Q single, K 2-limb) ----
        float sc[4][4];
#pragma unroll
        for (int na = 0; na < 4; na++)
#pragma unroll
            for (int r = 0; r < 4; r++) sc[na][r] = 0.f;

#pragma unroll
        for (int ks = 0; ks < 4; ks++) {
            uint32_t a[4];
            const uint32_t aoff = (uint32_t)((wid * 16 + (lane & 15)) * FSTB
                                             + ks * 32 + (lane >> 4) * 16);
            ldsm_x4(a[0], a[1], a[2], a[3], uQ + aoff);
#pragma unroll
            for (int np = 0; np < 2; np++) {
                const int m = lane >> 3;
                const int row = np * 16 + (m >> 1) * 8 + (lane & 7);
                const uint32_t boff = (uint32_t)(row * FSTB + ks * 32 + (m & 1) * 16);
                uint32_t b0h, b1h, b2h, b3h, b0l, b1l, b2l, b3l;
                ldsm_x4(b0h, b1h, b2h, b3h, uKh + boff);
                ldsm_x4(b0l, b1l, b2l, b3l, uKl + boff);
                const int na0 = np * 2, na1 = np * 2 + 1;
                mma_f16(sc[na0][0], sc[na0][1], sc[na0][2], sc[na0][3],
                        a[0], a[1], a[2], a[3], b0h, b1h);
                mma_f16(sc[na0][0], sc[na0][1], sc[na0][2], sc[na0][3],
                        a[0], a[1], a[2], a[3], b0l, b1l);
                mma_f16(sc[na1][0], sc[na1][1], sc[na1][2], sc[na1][3],
                        a[0], a[1], a[2], a[3], b2h, b3h);
                mma_f16(sc[na1][0], sc[na1][1], sc[na1][2], sc[na1][3],
                        a[0], a[1], a[2], a[3], b2l, b3l);
            }
        }

        // ---- scale (exp2 domain) + mask ----
#pragma unroll
        for (int na = 0; na < 4; na++) {
            const int kc = na * 8 + q * 2;
            const int mk0 = msj[kc], mk1 = msj[kc + 1];
            sc[na][0] = mk0 ? sc[na][0] * scale2 : -1e9f;
            sc[na][1] = mk1 ? sc[na][1] * scale2 : -1e9f;
            sc[na][2] = mk0 ? sc[na][2] * scale2 : -1e9f;
            sc[na][3] = mk1 ? sc[na][3] * scale2 : -1e9f;
        }

        // ---- online softmax (rows g, g+8; 4 lanes per row) ----
        float mx0 = -INFINITY, mx1 = -INFINITY;
#pragma unroll
        for (int na = 0; na < 4; na++) {
            mx0 = fmaxf(mx0, fmaxf(sc[na][0], sc[na][1]));
            mx1 = fmaxf(mx1, fmaxf(sc[na][2], sc[na][3]));
        }
        mx0 = fmaxf(mx0, __shfl_xor_sync(0xffffffffu, mx0, 1));
        mx0 = fmaxf(mx0, __shfl_xor_sync(0xffffffffu, mx0, 2));
        mx1 = fmaxf(mx1, __shfl_xor_sync(0xffffffffu, mx1, 1));
        mx1 = fmaxf(mx1, __shfl_xor_sync(0xffffffffu, mx1, 2));
        const float mn0 = fmaxf(m0, mx0), mn1 = fmaxf(m1, mx1);
        const float a0 = ex2(m0 - mn0), a1 = ex2(m1 - mn1);

        // P = exp2(sc - mn) in f16x2, fragments mma-ready
        uint32_t pA[4], pB[4];
        float sum0 = 0.f, sum1 = 0.f;
#pragma unroll
        for (int na = 0; na < 4; na++) {
            pA[na] = h2ex2(packh(sc[na][0] - mn0, sc[na][1] - mn0));
            pB[na] = h2ex2(packh(sc[na][2] - mn1, sc[na][3] - mn1));
            float2 f0 = __half22float2(*(__half2*)&pA[na]);
            float2 f1 = __half22float2(*(__half2*)&pB[na]);
            sum0 += f0.x + f0.y;
            sum1 += f1.x + f1.y;
        }
        sum0 += __shfl_xor_sync(0xffffffffu, sum0, 1);
        sum0 += __shfl_xor_sync(0xffffffffu, sum0, 2);
        sum1 += __shfl_xor_sync(0xffffffffu, sum1, 1);
        sum1 += __shfl_xor_sync(0xffffffffu, sum1, 2);
        l0 = l0 * a0 + sum0;
        l1 = l1 * a1 + sum1;
        m0 = mn0; m1 = mn1;
#pragma unroll
        for (int na = 0; na < 8; na++) {
            o[na][0] *= a0; o[na][1] *= a0;
            o[na][2] *= a1; o[na][3] *= a1;
        }

        // ---- GEMM2: O += P(fp16) * V(fp16 single), V via ldmatrix.x4.trans ----
#pragma unroll
        for (int kk = 0; kk < 2; kk++) {
            const uint32_t ph0 = pA[2*kk],   ph1 = pB[2*kk];
            const uint32_t ph2 = pA[2*kk+1], ph3 = pB[2*kk+1];
            const int m = lane >> 3;
#pragma unroll
            for (int np = 0; np < 4; np++) {
                const int row = kk * 16 + (m & 1) * 8 + (lane & 7);
                const int na0 = np * 2, na1 = np * 2 + 1;
                const uint32_t voff = (uint32_t)(row * FSTB + (np * 2 + (m >> 1)) * 16);
                uint32_t v0, v1, v2, v3;
                ldsm_x4t(v0, v1, v2, v3, uV + voff);
                mma_f16(o[na0][0], o[na0][1], o[na0][2], o[na0][3],
                        ph0, ph1, ph2, ph3, v0, v1);
                mma_f16(o[na1][0], o[na1][1], o[na1][2], o[na1][3],
                        ph0, ph1, ph2, ph3, v2, v3);
            }
        }
    }

    // ---- epilogue: divide by l, write context as single fp16 ----
    const float inv0 = 1.f / l0, inv1 = 1.f / l1;
    const int r0 = i0 + wid * 16 + g;
#pragma unroll
    for (int na = 0; na < 8; na++) {
        const int col = na * 8 + q * 2;
        *(uint32_t*)(C1 + base + (size_t)r0 * DD + col) =
            packh(o[na][0] * inv0, o[na][1] * inv0);
        *(uint32_t*)(C1 + base + (size_t)(r0 + 8) * DD + col) =
            packh(o[na][2] * inv1, o[na][3] * inv1);
    }
}

// ============================================================================
// kernel_launch
// ============================================================================
extern "C" void kernel_launch(void* const* d_in, const int* in_sizes, int n_in,
                              void* d_out, int out_size)
{
    const float* q    = (const float*)d_in[0];
    const float* k    = (const float*)d_in[1];
    const float* v    = (const float*)d_in[2];
    const int*   mask = (const int*)  d_in[3];
    const float* wq   = (const float*)d_in[4];
    const float* bq   = (const float*)d_in[5];
    const float* wk   = (const float*)d_in[6];
    const float* bk   = (const float*)d_in[7];
    const float* wv   = (const float*)d_in[8];
    const float* bv   = (const float*)d_in[9];
    const float* wo   = (const float*)d_in[10];
    const float* bo   = (const float*)d_in[11];
    float* out = (float*)d_out;

    __half *aq, *ak, *av;
    __half *wqh, *wql, *wkh, *wkl, *wvh, *wvl, *woh, *wol;
    __half *q1, *kh, *kl, *v1, *c1;
    cudaGetSymbolAddress((void**)&aq,  g_Aq);
    cudaGetSymbolAddress((void**)&ak,  g_Ak);
    cudaGetSymbolAddress((void**)&av,  g_Av);
    cudaGetSymbolAddress((void**)&wqh, g_WQh);
    cudaGetSymbolAddress((void**)&wql, g_WQl);
    cudaGetSymbolAddress((void**)&wkh, g_WKh);
    cudaGetSymbolAddress((void**)&wkl, g_WKl);
    cudaGetSymbolAddress((void**)&wvh, g_WVh);
    cudaGetSymbolAddress((void**)&wvl, g_WVl);
    cudaGetSymbolAddress((void**)&woh, g_WOh);
    cudaGetSymbolAddress((void**)&wol, g_WOl);
    cudaGetSymbolAddress((void**)&q1,  g_Q1);
    cudaGetSymbolAddress((void**)&kh,  g_Kh);
    cudaGetSymbolAddress((void**)&kl,  g_Kl);
    cudaGetSymbolAddress((void**)&v1,  g_V1);
    cudaGetSymbolAddress((void**)&c1,  g_C1);

    static bool attr_set = false;
    if (!attr_set) {
        cudaFuncSetAttribute(flash_tc, cudaFuncAttributeMaxDynamicSharedMemorySize,
                             FLASH_SMEM_BYTES);
        cudaFuncSetAttribute(gemm_qkv, cudaFuncAttributeMaxDynamicSharedMemorySize,
                             GS_TOTAL);
        cudaFuncSetAttribute(gemm_o, cudaFuncAttributeMaxDynamicSharedMemorySize,
                             GS_TOTAL);
        attr_set = true;
    }

    const int nA4 = NROWS * DD / 4;   // 1,048,576
    const int nW4 = DD * DD / 4;      //   262,144

    // Input conversions (fp16 single) and weight splits (fp16 2-limb)
    {
        ConvParams cp{};
        cp.x[0] = q; cp.y[0] = aq;
        cp.x[1] = k; cp.y[1] = ak;
        cp.x[2] = v; cp.y[2] = av;
        conv_half_multi<<<3 * nA4 / 256, 256>>>(cp, nA4);
    }
    {
        SplitHParams sp{};
        sp.x[0] = wq; sp.hi[0] = wqh; sp.lo[0] = wql;
        sp.x[1] = wk; sp.hi[1] = wkh; sp.lo[1] = wkl;
        sp.x[2] = wv; sp.hi[2] = wvh; sp.lo[2] = wvl;
        sp.x[3] = wo; sp.hi[3] = woh; sp.lo[3] = wol;
        split_half_multi<<<4 * nW4 / 256, 256>>>(sp, nW4);
    }

    // Batched Q/K/V projections: z=0 Q (single), z=1 K (2-limb), z=2 V (single)
    {
        QKVParams p{};
        p.A[0] = aq; p.Wh[0] = wqh; p.Wl[0] = wql; p.bias[0] = bq;
        p.C1[0] = q1; p.C2h[0] = nullptr; p.C2l[0] = nullptr;
        p.A[1] = ak; p.Wh[1] = wkh; p.Wl[1] = wkl; p.bias[1] = bk;
        p.C1[1] = nullptr; p.C2h[1] = kh; p.C2l[1] = kl;
        p.A[2] = av; p.Wh[2] = wvh; p.Wl[2] = wvl; p.bias[2] = bv;
        p.C1[2] = v1; p.C2h[2] = nullptr; p.C2l[2] = nullptr;
        dim3 tgrid(DD / 64, NROWS / 128, 3);   // (16, 32, 3) = 1536 CTAs
        gemm_qkv<<<tgrid, 256, GS_TOTAL>>>(p);
    }

    // Attention (128 threads, 64 q-rows per CTA, V single fp16)
    dim3 fgrid(SS / FBQ, HH, BB);        // (32, 16, 2) = 1024 CTAs
    flash_tc<<<fgrid, 128, FLASH_SMEM_BYTES>>>(q1, kh, kl, v1, mask, c1);

    // Output projection (fp32 out)
    dim3 ogrid(DD / 64, NROWS / 128);    // (16, 32) = 512 CTAs
    gemm_o<<<ogrid, 256, GS_TOTAL>>>(c1, woh, wol, bo, out);
}